// round 15
// baseline (speedup 1.0000x reference)
#include <cuda_runtime.h>
#include <cuda_bf16.h>
#include <stdint.h>
#include <cstdint>
#include <math.h>

// Problem constants
#define BB      16
#define NNODE   64
#define FIN     128
#define FHID    256
#define ODIM    768
#define HT      1536   // translate hidden
#define DR      770
#define HR      1540
#define NEDGE   65536  // B*N*N
#define NROW    1024   // B*N
#define TRI_B   2080   // 64*65/2 per batch
#define TRI_TOT 33280  // 16 * TRI_B (= 260 * 128)
#define HRP     1792   // W1r n-padding (7*256)

// ---------------- scratch (device globals; no runtime allocation) ----------
__device__ float g_agg[NROW * 256];
__device__ float g_U[NROW * HT];
__device__ float g_V[NROW * HT];
__device__ __align__(16) float g_c1[HT];
__device__ __align__(16) float g_c2[HT];
__device__ float g_r0[NROW], g_r1[NROW], g_c0s[NROW], g_c1s[NROW];
__device__ float g_sc[5];   // S0, S1, S00, S01, S11
__device__ int   g_tri[TRI_TOT];
__device__ __align__(16) __nv_bfloat16 g_xh[NROW * ODIM];
__device__ __align__(16) __nv_bfloat16 g_xl[NROW * ODIM];
__device__ __align__(16) __nv_bfloat16 g_hh[(size_t)TRI_TOT * HT];
__device__ __align__(16) __nv_bfloat16 g_hl[(size_t)TRI_TOT * HT];
__device__ __align__(16) __nv_bfloat16 g_ssh[(size_t)TRI_TOT * ODIM];
__device__ __align__(16) __nv_bfloat16 g_ssl[(size_t)TRI_TOT * ODIM];
// pre-packed B weights, [n][k] bf16 hi/lo
__device__ __align__(16) __nv_bfloat16 g_wuvh[3072 * 768], g_wuvl[3072 * 768];
__device__ __align__(16) __nv_bfloat16 g_w2h[768 * 1536],  g_w2l[768 * 1536];
__device__ __align__(16) __nv_bfloat16 g_w1rh[HRP * 768],  g_w1rl[HRP * 768];

__device__ __forceinline__ float elu_f(float x) {
    return x > 0.f ? x : (__expf(x) - 1.f);
}
static __device__ __forceinline__ uint32_t pack2(float a, float b) {
    __nv_bfloat162 h = __floats2bfloat162_rn(a, b);
    return *reinterpret_cast<uint32_t*>(&h);
}
static __device__ __forceinline__ uint32_t smem_addr(const void* p) {
    uint32_t a;
    asm("{ .reg .u64 t; cvta.to.shared.u64 t, %1; cvt.u32.u64 %0, t; }" : "=r"(a) : "l"(p));
    return a;
}
static __device__ __forceinline__ void mma16816(float* c, const uint32_t* a,
                                                const uint32_t* b) {
    asm volatile(
        "mma.sync.aligned.m16n8k16.row.col.f32.bf16.bf16.f32 "
        "{%0,%1,%2,%3}, {%4,%5,%6,%7}, {%8,%9}, {%0,%1,%2,%3};"
        : "+f"(c[0]), "+f"(c[1]), "+f"(c[2]), "+f"(c[3])
        : "r"(a[0]), "r"(a[1]), "r"(a[2]), "r"(a[3]), "r"(b[0]), "r"(b[1]));
}
static __device__ __forceinline__ void ldsm4(uint32_t* r, uint32_t addr) {
    asm volatile("ldmatrix.sync.aligned.m8n8.x4.shared.b16 {%0,%1,%2,%3}, [%4];"
        : "=r"(r[0]), "=r"(r[1]), "=r"(r[2]), "=r"(r[3]) : "r"(addr));
}
static __device__ __forceinline__ void ldsm2(uint32_t* r, uint32_t addr) {
    asm volatile("ldmatrix.sync.aligned.m8n8.x2.shared.b16 {%0,%1}, [%2];"
        : "=r"(r[0]), "=r"(r[1]) : "r"(addr));
}
static __device__ __forceinline__ void cpa16(uint32_t d, const void* s) {
    asm volatile("cp.async.ca.shared.global [%0], [%1], 16;" :: "r"(d), "l"(s));
}

#define KPAD    80   // bytes per k-row (40 bf16)
#define BUF_SZ  61440
#define AH_OFF  0
#define AL_OFF  10240
#define BH_OFF  20480
#define BL_OFF  40960

// ldmatrix lane-address components
#define LDSM_A_ROW(lane)  (((lane) & 7) + ((((lane) >> 3) & 1) << 3))
#define LDSM_A_KOFF(lane) ((((lane) >> 4) & 1) * 16)
#define LDSM_B_ROW(lane)  ((lane) & 7)
#define LDSM_B_KOFF(lane) ((((lane) >> 3) & 1) * 16)

// stage one chunk (A: 128x32, B: 256x32, hi+lo) into buffer bufb, commit group
#define STAGE_CHUNK(bufb, pAH, pAL, k0, BHsrc, BLsrc, nbase, SRCK)              \
    do {                                                                        \
        cpa16((bufb) + AH_OFF + mrow * KPAD + kq8 * 2, (pAH) + (k0));           \
        cpa16((bufb) + AL_OFF + mrow * KPAD + kq8 * 2, (pAL) + (k0));           \
        _Pragma("unroll")                                                       \
        for (int it_ = 0; it_ < 2; it_++) {                                     \
            int idx_ = t + it_ * 512;                                           \
            int n_ = idx_ >> 2, seg_ = idx_ & 3;                                \
            size_t so_ = (size_t)((nbase) + n_) * (SRCK) + (k0) + seg_ * 8;     \
            cpa16((bufb) + BH_OFF + n_ * KPAD + seg_ * 16, (BHsrc) + so_);      \
            cpa16((bufb) + BL_OFF + n_ * KPAD + seg_ * 16, (BLsrc) + so_);      \
        }                                                                       \
        asm volatile("cp.async.commit_group;");                                 \
    } while (0)

// One k-step of the 3-product split GEMM
#define SPLIT_MMA_KSTEP(aBH, aBL, bBH, bBL, ksb, acc)                          \
    do {                                                                       \
        uint32_t af[4][4], bh[4][2], bl[4][2];                                 \
        _Pragma("unroll")                                                      \
        for (int tm = 0; tm < 4; tm++) ldsm4(af[tm], (aBH) + tm * 16 * KPAD + (ksb)); \
        _Pragma("unroll")                                                      \
        for (int tn = 0; tn < 4; tn++) ldsm2(bh[tn], (bBH) + tn * 8 * KPAD + (ksb)); \
        _Pragma("unroll")                                                      \
        for (int tn = 0; tn < 4; tn++) ldsm2(bl[tn], (bBL) + tn * 8 * KPAD + (ksb)); \
        _Pragma("unroll")                                                      \
        for (int tm = 0; tm < 4; tm++)                                         \
            _Pragma("unroll")                                                  \
            for (int tn = 0; tn < 4; tn++)                                     \
                mma16816(acc[tm][tn], af[tm], bh[tn]);                         \
        _Pragma("unroll")                                                      \
        for (int tm = 0; tm < 4; tm++)                                         \
            _Pragma("unroll")                                                  \
            for (int tn = 0; tn < 4; tn++)                                     \
                mma16816(acc[tm][tn], af[tm], bl[tn]);                         \
        _Pragma("unroll")                                                      \
        for (int tm = 0; tm < 4; tm++) ldsm4(af[tm], (aBL) + tm * 16 * KPAD + (ksb)); \
        _Pragma("unroll")                                                      \
        for (int tm = 0; tm < 4; tm++)                                         \
            _Pragma("unroll")                                                  \
            for (int tn = 0; tn < 4; tn++)                                     \
                mma16816(acc[tm][tn], af[tm], bh[tn]);                         \
    } while (0)

// ---------------- weight pack kernels ---------------------------------------
__global__ void k_pack_uv(const float* __restrict__ W1t) {
    int idx = blockIdx.x * 256 + threadIdx.x;
    int n = idx / 768, k = idx - n * 768;
    int isV = (n >= 1536);
    int col = isV ? n - 1536 : n;
    float v = W1t[(size_t)((isV ? 770 : 2) + k) * HT + col];
    __nv_bfloat16 h = __float2bfloat16(v);
    g_wuvh[idx] = h;
    g_wuvl[idx] = __float2bfloat16(v - __bfloat162float(h));
}
__global__ void k_pack_w2(const float* __restrict__ W2t) {
    int idx = blockIdx.x * 256 + threadIdx.x;
    int n = idx / 1536, k = idx - n * 1536;
    float v = W2t[(size_t)k * 768 + n];
    __nv_bfloat16 h = __float2bfloat16(v);
    g_w2h[idx] = h;
    g_w2l[idx] = __float2bfloat16(v - __bfloat162float(h));
}
__global__ void k_pack_w1r(const float* __restrict__ W1r) {
    int idx = blockIdx.x * 256 + threadIdx.x;
    int n = idx / 768, k = idx - n * 768;
    float v = (n < HR) ? W1r[(size_t)(2 + k) * HR + n] : 0.f;
    __nv_bfloat16 h = __float2bfloat16(v);
    g_w1rh[idx] = h;
    g_w1rl[idx] = __float2bfloat16(v - __bfloat162float(h));
}

// ---------------- kernel 0: triangle rank -> edge table ---------------------
__global__ void k_trimap() {
    int e = blockIdx.x * 1024 + threadIdx.x;
    int b = e >> 12, i = (e >> 6) & 63, j = e & 63;
    if (i <= j) {
        int rank = b * TRI_B + i * (129 - i) / 2 + (j - i);
        g_tri[rank] = e;
    }
}

// ---------------- kernel 1: agg --------------------------------------------
__global__ void k_agg(const float* __restrict__ x, const float* __restrict__ adjs,
                      const float* __restrict__ flags) {
    int bi = blockIdx.x;
    int b = bi >> 6, i = bi & 63;
    int f = threadIdx.x;
    __shared__ float a0s[64], a1s[64];
    float fi = flags[b * 64 + i];
    if (threadIdx.x < 64) {
        int j = threadIdx.x;
        float fj = flags[b * 64 + j];
        float a = adjs[(size_t)bi * 64 + j];
        float m = fi * fj;
        a0s[j] = a * m;
        a1s[j] = (1.f - a) * m;
    }
    __syncthreads();
    float s0 = 0.f, s1 = 0.f;
    const float* xb = x + (size_t)b * NNODE * FIN;
    #pragma unroll 4
    for (int j = 0; j < 64; j++) {
        float xv = xb[j * FIN + f];
        s0 += a0s[j] * xv;
        s1 += a1s[j] * xv;
    }
    g_agg[bi * 256 + f] = s0;
    g_agg[bi * 256 + 128 + f] = s1;
}

// ---------------- kernel 2: GIN MLPs -> x_o (+ bf16 hi/lo split) ------------
__global__ void k_gin(const float* __restrict__ x, const float* __restrict__ flags,
                      const float* __restrict__ Wg, const float* __restrict__ bg,
                      const float* __restrict__ Wout, const float* __restrict__ bout,
                      float* __restrict__ out_xo) {
    __shared__ float aggs[8][256];
    __shared__ float xs[8][128];
    __shared__ float hs[8][256];
    __shared__ float fl[8];
    int r0 = blockIdx.x * 8;
    int t = threadIdx.x;
    for (int idx = t; idx < 8 * 256; idx += 256)
        aggs[idx >> 8][idx & 255] = g_agg[r0 * 256 + idx];
    for (int idx = t; idx < 8 * 128; idx += 256)
        xs[idx >> 7][idx & 127] = x[(size_t)r0 * 128 + idx];
    if (t < 8) fl[t] = flags[r0 + t];
    __syncthreads();
    {
        float acc[8];
        float bgv = bg[t];
        #pragma unroll
        for (int r = 0; r < 8; r++) acc[r] = bgv;
        for (int k = 0; k < 256; k++) {
            float w = Wg[k * 256 + t];
            #pragma unroll
            for (int r = 0; r < 8; r++) acc[r] += aggs[r][k] * w;
        }
        #pragma unroll
        for (int r = 0; r < 8; r++) hs[r][t] = elu_f(acc[r]) * fl[r];
    }
    __syncthreads();
    float acc[3][8];
    #pragma unroll
    for (int c = 0; c < 3; c++) {
        float bo = bout[t + c * 256];
        #pragma unroll
        for (int r = 0; r < 8; r++) acc[c][r] = bo;
    }
    for (int k = 0; k < 128; k++) {
        float o[8];
        #pragma unroll
        for (int r = 0; r < 8; r++) o[r] = xs[r][k];
        #pragma unroll
        for (int c = 0; c < 3; c++) {
            float w = Wout[k * 768 + t + c * 256];
            #pragma unroll
            for (int r = 0; r < 8; r++) acc[c][r] += o[r] * w;
        }
    }
    for (int k = 0; k < 256; k++) {
        float o[8];
        #pragma unroll
        for (int r = 0; r < 8; r++) o[r] = hs[r][k];
        #pragma unroll
        for (int c = 0; c < 3; c++) {
            float w = Wout[(128 + k) * 768 + t + c * 256];
            #pragma unroll
            for (int r = 0; r < 8; r++) acc[c][r] += o[r] * w;
        }
    }
    #pragma unroll
    for (int c = 0; c < 3; c++)
        #pragma unroll
        for (int r = 0; r < 8; r++) {
            size_t idx = (size_t)(r0 + r) * 768 + t + c * 256;
            float val = tanhf(acc[c][r]) * fl[r];
            out_xo[idx] = val;
            __nv_bfloat16 h = __float2bfloat16(val);
            g_xh[idx] = h;
            g_xl[idx] = __float2bfloat16(val - __bfloat162float(h));
        }
}

// ---------------- kernel 3: U,V via 2-stage pipelined mma (R13) --------------
#define UV_SMEM (2 * BUF_SZ)

__global__ void __launch_bounds__(512, 1)
k_uv_mma() {
    extern __shared__ char sm[];
    uint32_t sb = smem_addr(sm);
    int t = threadIdx.x;
    int m0 = blockIdx.y * 128;
    int ng0 = blockIdx.x * 256;
    const int isU = (ng0 < HT);

    int wid = t >> 5, lane = t & 31;
    int mw = (wid & 1) * 64, nw = (wid >> 1) * 32;
    int row4 = lane >> 2, quad = lane & 3;
    int mrow = t >> 2, kq8 = (t & 3) * 8;
    const __nv_bfloat16* pAH = g_xh + (size_t)(m0 + mrow) * 768 + kq8;
    const __nv_bfloat16* pAL = g_xl + (size_t)(m0 + mrow) * 768 + kq8;
    int laneA = (mw + LDSM_A_ROW(lane)) * KPAD + LDSM_A_KOFF(lane);
    int laneB = (nw + LDSM_B_ROW(lane)) * KPAD + LDSM_B_KOFF(lane);

    float acc[4][4][4];
    #pragma unroll
    for (int tm = 0; tm < 4; tm++)
        #pragma unroll
        for (int tn = 0; tn < 4; tn++)
            #pragma unroll
            for (int q = 0; q < 4; q++) acc[tm][tn][q] = 0.f;

    STAGE_CHUNK(sb, pAH, pAL, 0, g_wuvh, g_wuvl, ng0, 768);
    for (int c = 0; c < 24; c++) {
        uint32_t cur = sb + (c & 1) * BUF_SZ;
        uint32_t nxt = sb + ((c + 1) & 1) * BUF_SZ;
        __syncthreads();
        if (c + 1 < 24) {
            STAGE_CHUNK(nxt, pAH, pAL, (c + 1) * 32, g_wuvh, g_wuvl, ng0, 768);
            asm volatile("cp.async.wait_group 1;" ::: "memory");
        } else {
            asm volatile("cp.async.wait_group 0;" ::: "memory");
        }
        __syncthreads();
        #pragma unroll
        for (int ks = 0; ks < 2; ks++)
            SPLIT_MMA_KSTEP(cur + AH_OFF + laneA, cur + AL_OFF + laneA,
                            cur + BH_OFF + laneB, cur + BL_OFF + laneB, ks * 32, acc);
    }

    float* Obase = (isU ? g_U : g_V);
    int c0 = isU ? ng0 : ng0 - HT;
    #pragma unroll
    for (int tm = 0; tm < 4; tm++) {
        int gr = m0 + mw + tm * 16 + row4;
        #pragma unroll
        for (int tn = 0; tn < 4; tn++) {
            int gc = c0 + nw + tn * 8 + quad * 2;
            float* p0 = Obase + (size_t)gr * HT + gc;
            float* p1 = Obase + (size_t)(gr + 8) * HT + gc;
            *(float2*)p0 = make_float2(acc[tm][tn][0], acc[tm][tn][1]);
            *(float2*)p1 = make_float2(acc[tm][tn][2], acc[tm][tn][3]);
        }
    }
}

// ---------------- kernel 4a: adjacency sums (analytic BN stats, part A) -----
__global__ void k_statA(const float* __restrict__ adjs, const float* __restrict__ flags) {
    int bi = threadIdx.x;          // 1024 threads, 1 block
    int b = bi >> 6, i = bi & 63;
    float fi = flags[b * 64 + i];
    float r0 = 0.f, r1 = 0.f, c0 = 0.f, c1 = 0.f;
    float s0 = 0.f, s1 = 0.f, s00 = 0.f, s01 = 0.f, s11 = 0.f;
    for (int j = 0; j < 64; j++) {
        float fj = flags[b * 64 + j];
        float m = fi * fj;
        float a = adjs[(size_t)(b * 64 + i) * 64 + j];
        float a0 = a * m, a1 = (1.f - a) * m;
        r0 += a0; r1 += a1;
        s0 += a0; s1 += a1;
        s00 += a0 * a0; s01 += a0 * a1; s11 += a1 * a1;
        float at = adjs[(size_t)(b * 64 + j) * 64 + i];
        c0 += at * m; c1 += (1.f - at) * m;
    }
    g_r0[bi] = r0; g_r1[bi] = r1; g_c0s[bi] = c0; g_c1s[bi] = c1;
    __shared__ float red[1024];
    float vals[5] = {s0, s1, s00, s01, s11};
    for (int v = 0; v < 5; v++) {
        red[bi] = vals[v];
        __syncthreads();
        for (int off = 512; off > 0; off >>= 1) {
            if (bi < off) red[bi] += red[bi + off];
            __syncthreads();
        }
        if (bi == 0) g_sc[v] = red[0];
        __syncthreads();
    }
}

// ---------------- kernel 4b: per-column BN constants (part B) ---------------
__global__ void k_statB(const float* __restrict__ W1t, const float* __restrict__ b1t,
                        const float* __restrict__ gamma, const float* __restrict__ beta) {
    int k = blockIdx.x * 128 + threadIdx.x;   // 12 blocks x 128 -> 1536
    float w0 = W1t[k], w1 = W1t[HT + k];
    float sumz = 0.f, sqb = 0.f, T0 = 0.f, T1 = 0.f;
    for (int b = 0; b < 16; b++) {
        float ub = 0.f, vb = 0.f, u2 = 0.f, v2 = 0.f;
        #pragma unroll 4
        for (int r = 0; r < 64; r++) {
            int bi = b * 64 + r;
            float u = g_U[(size_t)bi * HT + k];
            float v = g_V[(size_t)bi * HT + k];
            ub += u; vb += v; u2 += u * u; v2 += v * v;
            T0 += u * g_r0[bi] + v * g_c0s[bi];
            T1 += u * g_r1[bi] + v * g_c1s[bi];
        }
        sumz += 64.f * (ub + vb);
        sqb += 64.f * (u2 + v2) + 2.f * ub * vb;
    }
    float S0 = g_sc[0], S1 = g_sc[1], S00 = g_sc[2], S01 = g_sc[3], S11 = g_sc[4];
    float sz = sumz + S0 * w0 + S1 * w1;
    float sq = sqb + 2.f * (w0 * T0 + w1 * T1)
             + S00 * w0 * w0 + 2.f * S01 * w0 * w1 + S11 * w1 * w1;
    const float inv = 1.f / 65536.f;
    float mu_z = sz * inv;
    float var = fmaxf(sq * inv - mu_z * mu_z, 0.f);
    float mu = mu_z + b1t[k];
    float c1 = gamma[k] * rsqrtf(var + 1e-5f);
    g_c1[k] = c1;
    g_c2[k] = beta[k] - mu * c1;
}

// ---------------- kernel 5b: h2sum on triangle (balanced pairs) -------------
__global__ void __launch_bounds__(384)
k_agen_tri(const float* __restrict__ adjs, const float* __restrict__ flags,
           const float* __restrict__ W1t) {
    int blk = blockIdx.x;
    int b = blk >> 5, p = blk & 31;
    int c4 = threadIdx.x * 4;
    float4 w0 = __ldg((const float4*)(W1t + c4));
    float4 w1 = __ldg((const float4*)(W1t + HT + c4));
    float4 c1 = *(const float4*)(g_c1 + c4);
    float4 c2 = *(const float4*)(g_c2 + c4);
    #pragma unroll
    for (int half = 0; half < 2; half++) {
        int i = half ? (63 - p) : p;
        int bi = b * 64 + i;
        float4 ui = *(const float4*)(g_U + (size_t)bi * HT + c4);
        float4 vi = *(const float4*)(g_V + (size_t)bi * HT + c4);
        float fi = __ldg(flags + b * 64 + i);
        size_t rank0 = (size_t)b * TRI_B + i * (129 - i) / 2;
        for (int j = i; j < 64; j++) {
            float fj = __ldg(flags + b * 64 + j);
            float mk = fi * fj;
            float aij = __ldg(adjs + (size_t)b * 4096 + i * 64 + j);
            float aji = __ldg(adjs + (size_t)b * 4096 + j * 64 + i);
            float a0ij = aij * mk, a1ij = (1.f - aij) * mk;
            float a0ji = aji * mk, a1ji = (1.f - aji) * mk;
            float4 uj = *(const float4*)(g_U + (size_t)(b * 64 + j) * HT + c4);
            float4 vj = *(const float4*)(g_V + (size_t)(b * 64 + j) * HT + c4);
            float s0 = elu_f((ui.x + vj.x + a0ij * w0.x + a1ij * w1.x) * c1.x + c2.x)
                     + elu_f((uj.x + vi.x + a0ji * w0.x + a1ji * w1.x) * c1.x + c2.x);
            float s1 = elu_f((ui.y + vj.y + a0ij * w0.y + a1ij * w1.y) * c1.y + c2.y)
                     + elu_f((uj.y + vi.y + a0ji * w0.y + a1ji * w1.y) * c1.y + c2.y);
            float s2 = elu_f((ui.z + vj.z + a0ij * w0.z + a1ij * w1.z) * c1.z + c2.z)
                     + elu_f((uj.z + vi.z + a0ji * w0.z + a1ji * w1.z) * c1.z + c2.z);
            float s3 = elu_f((ui.w + vj.w + a0ij * w0.w + a1ij * w1.w) * c1.w + c2.w)
                     + elu_f((uj.w + vi.w + a0ji * w0.w + a1ji * w1.w) * c1.w + c2.w);
            float r0 = s0 - __bfloat162float(__float2bfloat16(s0));
            float r1 = s1 - __bfloat162float(__float2bfloat16(s1));
            float r2 = s2 - __bfloat162float(__float2bfloat16(s2));
            float r3 = s3 - __bfloat162float(__float2bfloat16(s3));
            size_t row = (rank0 + (j - i)) * HT + c4;
            *(uint2*)(g_hh + row) = make_uint2(pack2(s0, s1), pack2(s2, s3));
            *(uint2*)(g_hl + row) = make_uint2(pack2(r0, r1), pack2(r2, r3));
        }
    }
}

// ---------------- kernel 6: triangle translate GEMM -> S (R13) ---------------
#define GP_MKS  (2 * BUF_SZ)
#define GP_SMEM (2 * BUF_SZ + 512)

__global__ void __launch_bounds__(512, 1)
k_gemm2_tri(const float* __restrict__ flags, const float* __restrict__ b2t) {
    extern __shared__ char sm[];
    uint32_t sb = smem_addr(sm);
    float* mks = (float*)(sm + GP_MKS);
    int t = threadIdx.x;
    int m0 = blockIdx.y * 128, n0g = blockIdx.x * 256;

    if (t < 128) {
        int e = __ldg(g_tri + m0 + t);
        int b = e >> 12, i = (e >> 6) & 63, j = e & 63;
        mks[t] = __ldg(flags + b * 64 + i) * __ldg(flags + b * 64 + j);
    }

    int wid = t >> 5, lane = t & 31;
    int mw = (wid & 1) * 64, nw = (wid >> 1) * 32;
    int row4 = lane >> 2, quad = lane & 3;
    int mrow = t >> 2, kq8 = (t & 3) * 8;
    const __nv_bfloat16* pAH = g_hh + (size_t)(m0 + mrow) * HT + kq8;
    const __nv_bfloat16* pAL = g_hl + (size_t)(m0 + mrow) * HT + kq8;
    int laneA = (mw + LDSM_A_ROW(lane)) * KPAD + LDSM_A_KOFF(lane);
    int laneB = (nw + LDSM_B_ROW(lane)) * KPAD + LDSM_B_KOFF(lane);

    float acc[4][4][4];
    #pragma unroll
    for (int tm = 0; tm < 4; tm++)
        #pragma unroll
        for (int tn = 0; tn < 4; tn++)
            #pragma unroll
            for (int q = 0; q < 4; q++) acc[tm][tn][q] = 0.f;

    STAGE_CHUNK(sb, pAH, pAL, 0, g_w2h, g_w2l, n0g, 1536);
    for (int c = 0; c < 48; c++) {
        uint32_t cur = sb + (c & 1) * BUF_SZ;
        uint32_t nxt = sb + ((c + 1) & 1) * BUF_SZ;
        __syncthreads();
        if (c + 1 < 48) {
            STAGE_CHUNK(nxt, pAH, pAL, (c + 1) * 32, g_w2h, g_w2l, n0g, 1536);
            asm volatile("cp.async.wait_group 1;" ::: "memory");
        } else {
            asm volatile("cp.async.wait_group 0;" ::: "memory");
        }
        __syncthreads();
        #pragma unroll
        for (int ks = 0; ks < 2; ks++)
            SPLIT_MMA_KSTEP(cur + AH_OFF + laneA, cur + AL_OFF + laneA,
                            cur + BH_OFF + laneB, cur + BL_OFF + laneB, ks * 32, acc);
    }

    #pragma unroll
    for (int tm = 0; tm < 4; tm++) {
        int r0 = mw + tm * 16 + row4;
        float mk0 = mks[r0], mk1 = mks[r0 + 8];
        size_t gr0 = (size_t)(m0 + r0) * 768;
        size_t gr1 = (size_t)(m0 + r0 + 8) * 768;
        #pragma unroll
        for (int tn = 0; tn < 4; tn++) {
            int gc = n0g + nw + tn * 8 + quad * 2;
            float bx = 2.f * __ldg(b2t + gc), by = 2.f * __ldg(b2t + gc + 1);
            float s00 = (acc[tm][tn][0] + bx) * mk0, s01 = (acc[tm][tn][1] + by) * mk0;
            float s10 = (acc[tm][tn][2] + bx) * mk1, s11 = (acc[tm][tn][3] + by) * mk1;
            float r00 = s00 - __bfloat162float(__float2bfloat16(s00));
            float r01 = s01 - __bfloat162float(__float2bfloat16(s01));
            float r10 = s10 - __bfloat162float(__float2bfloat16(s10));
            float r11 = s11 - __bfloat162float(__float2bfloat16(s11));
            *(uint32_t*)(g_ssh + gr0 + gc) = pack2(s00, s01);
            *(uint32_t*)(g_ssl + gr0 + gc) = pack2(r00, r01);
            *(uint32_t*)(g_ssh + gr1 + gc) = pack2(s10, s11);
            *(uint32_t*)(g_ssl + gr1 + gc) = pack2(r10, r11);
        }
    }
}

// ---------------- kernel 7: triangle final_read_score (R13) -----------------
#define ST_A0IJ (2 * BUF_SZ)
#define ST_A1IJ (2 * BUF_SZ + 512)
#define ST_A0JI (2 * BUF_SZ + 1024)
#define ST_A1JI (2 * BUF_SZ + 1536)
#define ST_ESM  (2 * BUF_SZ + 2048)
#define ST_RED  (2 * BUF_SZ + 2560)
#define ST_SMEM (2 * BUF_SZ + 2560 + 8192)

__global__ void __launch_bounds__(512, 1)
k_score_tri(const float* __restrict__ adjs, const float* __restrict__ flags,
            const float* __restrict__ W1r, const float* __restrict__ b1r,
            const float* __restrict__ W2r, const float* __restrict__ b2r,
            float* __restrict__ out_score) {
    extern __shared__ char sm[];
    uint32_t sb = smem_addr(sm);
    float* a0ijs = (float*)(sm + ST_A0IJ);
    float* a1ijs = (float*)(sm + ST_A1IJ);
    float* a0jis = (float*)(sm + ST_A0JI);
    float* a1jis = (float*)(sm + ST_A1JI);
    int*   esm   = (int*)(sm + ST_ESM);
    float* red   = (float*)(sm + ST_RED);
    int t = threadIdx.x;
    int m0 = blockIdx.x * 128;

    if (t < 128) {
        int e = __ldg(g_tri + m0 + t);
        esm[t] = e;
        int b = e >> 12, i = (e >> 6) & 63, j = e & 63;
        float mk = __ldg(flags + b * 64 + i) * __ldg(flags + b * 64 + j);
        float aij = __ldg(adjs + e);
        float aji = __ldg(adjs + (b << 12) + (j << 6) + i);
        a0ijs[t] = aij * mk; a1ijs[t] = (1.f - aij) * mk;
        a0jis[t] = aji * mk; a1jis[t] = (1.f - aji) * mk;
    }

    int wid = t >> 5, lane = t & 31;
    int mw = (wid & 1) * 64, nw = (wid >> 1) * 32;
    int row4 = lane >> 2, quad = lane & 3;
    int mrow = t >> 2, kq8 = (t & 3) * 8;
    const __nv_bfloat16* pSH = g_ssh + (size_t)(m0 + mrow) * 768 + kq8;
    const __nv_bfloat16* pSL = g_ssl + (size_t)(m0 + mrow) * 768 + kq8;
    int laneA = (mw + LDSM_A_ROW(lane)) * KPAD + LDSM_A_KOFF(lane);
    int laneB = (nw + LDSM_B_ROW(lane)) * KPAD + LDSM_B_KOFF(lane);

    float sij[4][2], sji[4][2];
    #pragma unroll
    for (int tm = 0; tm < 4; tm++) {
        sij[tm][0] = 0.f; sij[tm][1] = 0.f;
        sji[tm][0] = 0.f; sji[tm][1] = 0.f;
    }
    __syncthreads();

    STAGE_CHUNK(sb, pSH, pSL, 0, g_w1rh, g_w1rl, 0, 768);
    for (int nc = 0; nc < 7; nc++) {
        int n0 = nc * 256;
        float acc[4][4][4];
        #pragma unroll
        for (int tn = 0; tn < 4; tn++)
            #pragma unroll
            for (int cq = 0; cq < 2; cq++) {
                int n = n0 + nw + tn * 8 + quad * 2 + cq;
                float br = (n < HR) ? __ldg(b1r + n) : 0.f;
                #pragma unroll
                for (int tm = 0; tm < 4; tm++) {
                    acc[tm][tn][cq] = br;
                    acc[tm][tn][2 + cq] = br;
                }
            }
        for (int c = 0; c < 24; c++) {
            uint32_t cur = sb + (c & 1) * BUF_SZ;
            uint32_t nxt = sb + ((c + 1) & 1) * BUF_SZ;
            __syncthreads();
            if (c + 1 < 24) {
                STAGE_CHUNK(nxt, pSH, pSL, (c + 1) * 32, g_w1rh, g_w1rl, n0, 768);
                asm volatile("cp.async.wait_group 1;" ::: "memory");
            } else {
                asm volatile("cp.async.wait_group 0;" ::: "memory");
            }
            __syncthreads();
            #pragma unroll
            for (int ks = 0; ks < 2; ks++)
                SPLIT_MMA_KSTEP(cur + AH_OFF + laneA, cur + AL_OFF + laneA,
                                cur + BH_OFF + laneB, cur + BL_OFF + laneB, ks * 32, acc);
        }
        // prefetch next nc's chunk 0 (buffer 0 free) before epilogue
        if (nc + 1 < 7)
            STAGE_CHUNK(sb, pSH, pSL, 0, g_w1rh, g_w1rl, (nc + 1) * 256, 768);
        // epilogue: elu both orientations, dot with W2r
        #pragma unroll
        for (int tn = 0; tn < 4; tn++)
            #pragma unroll
            for (int cq = 0; cq < 2; cq++) {
                int n = n0 + nw + tn * 8 + quad * 2 + cq;
                bool ok = n < HR;
                float w0 = ok ? __ldg(W1r + n) : 0.f;
                float w1 = ok ? __ldg(W1r + HR + n) : 0.f;
                float w2 = ok ? __ldg(W2r + n) : 0.f;
                #pragma unroll
                for (int tm = 0; tm < 4; tm++) {
                    int r0 = mw + tm * 16 + row4;
                    float g0 = acc[tm][tn][cq], g1 = acc[tm][tn][2 + cq];
                    sij[tm][0] += elu_f(g0 + a0ijs[r0] * w0 + a1ijs[r0] * w1) * w2;
                    sji[tm][0] += elu_f(g0 + a0jis[r0] * w0 + a1jis[r0] * w1) * w2;
                    sij[tm][1] += elu_f(g1 + a0ijs[r0 + 8] * w0 + a1ijs[r0 + 8] * w1) * w2;
                    sji[tm][1] += elu_f(g1 + a0jis[r0 + 8] * w0 + a1jis[r0 + 8] * w1) * w2;
                }
            }
    }
    #pragma unroll
    for (int off = 1; off <= 2; off <<= 1)
        #pragma unroll
        for (int tm = 0; tm < 4; tm++) {
            sij[tm][0] += __shfl_xor_sync(0xffffffffu, sij[tm][0], off);
            sij[tm][1] += __shfl_xor_sync(0xffffffffu, sij[tm][1], off);
            sji[tm][0] += __shfl_xor_sync(0xffffffffu, sji[tm][0], off);
            sji[tm][1] += __shfl_xor_sync(0xffffffffu, sji[tm][1], off);
        }
    __syncthreads();
    if (quad == 0) {
        int wn = wid >> 1;
        #pragma unroll
        for (int tm = 0; tm < 4; tm++) {
            int r0 = mw + tm * 16 + row4;
            red[r0 * 8 + wn] = sij[tm][0];
            red[(r0 + 8) * 8 + wn] = sij[tm][1];
            red[1024 + r0 * 8 + wn] = sji[tm][0];
            red[1024 + (r0 + 8) * 8 + wn] = sji[tm][1];
        }
    }
    __syncthreads();
    if (t < 128) {
        float s1 = 0.f, s2 = 0.f;
        #pragma unroll
        for (int w8 = 0; w8 < 8; w8++) {
            s1 += red[t * 8 + w8];
            s2 += red[1024 + t * 8 + w8];
        }
        int e = esm[t];
        int b = e >> 12, i = (e >> 6) & 63, j = e & 63;
        float b2 = b2r[0];
        out_score[e] = (i == j) ? 0.f : (s1 + b2);
        if (i != j)
            out_score[(b << 12) + (j << 6) + i] = s2 + b2;
    }
}

// ---------------- launch -----------------------------------------------------
extern "C" void kernel_launch(void* const* d_in, const int* in_sizes, int n_in,
                              void* d_out, int out_size) {
    const float* x     = (const float*)d_in[0];
    const float* adjs  = (const float*)d_in[1];
    const float* flags = (const float*)d_in[2];
    const float* Wg    = (const float*)d_in[3];
    const float* bg    = (const float*)d_in[4];
    const float* Wout  = (const float*)d_in[5];
    const float* bout  = (const float*)d_in[6];
    const float* W1t   = (const float*)d_in[7];
    const float* b1t   = (const float*)d_in[8];
    const float* gamma = (const float*)d_in[9];
    const float* beta  = (const float*)d_in[10];
    const float* W2t   = (const float*)d_in[11];
    const float* b2t   = (const float*)d_in[12];
    const float* W1r   = (const float*)d_in[13];
    const float* b1r   = (const float*)d_in[14];
    const float* W2r   = (const float*)d_in[15];
    const float* b2r   = (const float*)d_in[16];

    float* out_score = (float*)d_out;             // [B,N,N] = 65536
    float* out_xo    = (float*)d_out + NEDGE;     // [B,N,768]

    cudaFuncSetAttribute(k_uv_mma, cudaFuncAttributeMaxDynamicSharedMemorySize, UV_SMEM);
    cudaFuncSetAttribute(k_gemm2_tri, cudaFuncAttributeMaxDynamicSharedMemorySize, GP_SMEM);
    cudaFuncSetAttribute(k_score_tri, cudaFuncAttributeMaxDynamicSharedMemorySize, ST_SMEM);

    k_pack_uv<<<3072 * 768 / 256, 256>>>(W1t);
    k_pack_w2<<<768 * 1536 / 256, 256>>>(W2t);
    k_pack_w1r<<<HRP * 768 / 256, 256>>>(W1r);
    k_trimap<<<64, 1024>>>();
    k_statA<<<1, 1024>>>(adjs, flags);
    k_agg<<<NROW, 128>>>(x, adjs, flags);
    k_gin<<<NROW / 8, 256>>>(x, flags, Wg, bg, Wout, bout, out_xo);
    k_uv_mma<<<dim3(12, 8), 512, UV_SMEM>>>();
    k_statB<<<12, 128>>>(W1t, b1t, gamma, beta);
    k_agen_tri<<<512, 384>>>(adjs, flags, W1t);
    k_gemm2_tri<<<dim3(3, 260), 512, GP_SMEM>>>(flags, b2t);
    k_score_tri<<<260, 512, ST_SMEM>>>(adjs, flags, W1r, b1r, W2r, b2r, out_score);
}

// round 16
// speedup vs baseline: 1.1099x; 1.1099x over previous
#include <cuda_runtime.h>
#include <cuda_bf16.h>
#include <stdint.h>
#include <cstdint>
#include <math.h>

// Problem constants
#define BB      16
#define NNODE   64
#define FIN     128
#define FHID    256
#define ODIM    768
#define HT      1536   // translate hidden
#define DR      770
#define HR      1540
#define NEDGE   65536  // B*N*N
#define NROW    1024   // B*N
#define TRI_B   2080   // 64*65/2 per batch
#define TRI_TOT 33280  // 16 * TRI_B (= 260 * 128)
#define HRP     1792   // W1r n-padding (7*256)

// ---------------- scratch (device globals; no runtime allocation) ----------
__device__ float g_agg[NROW * 256];
__device__ float g_U[NROW * HT];
__device__ float g_V[NROW * HT];
__device__ float g_part[4 * 16 * HT];   // SoA stats partials [v][b][k]
__device__ float g_scp[16 * 5];         // per-batch scalar partials
__device__ __align__(16) float g_c1[HT];
__device__ __align__(16) float g_c2[HT];
__device__ float g_r0[NROW], g_r1[NROW], g_c0s[NROW], g_c1s[NROW];
__device__ int   g_tri[TRI_TOT];
__device__ __align__(16) __nv_bfloat16 g_xh[NROW * ODIM];
__device__ __align__(16) __nv_bfloat16 g_xl[NROW * ODIM];
__device__ __align__(16) __nv_bfloat16 g_hh[(size_t)TRI_TOT * HT];
__device__ __align__(16) __nv_bfloat16 g_hl[(size_t)TRI_TOT * HT];
__device__ __align__(16) __nv_bfloat16 g_ssh[(size_t)TRI_TOT * ODIM];
__device__ __align__(16) __nv_bfloat16 g_ssl[(size_t)TRI_TOT * ODIM];
// pre-packed B weights, [n][k] bf16 hi/lo
__device__ __align__(16) __nv_bfloat16 g_wuvh[3072 * 768], g_wuvl[3072 * 768];
__device__ __align__(16) __nv_bfloat16 g_w2h[768 * 1536],  g_w2l[768 * 1536];
__device__ __align__(16) __nv_bfloat16 g_w1rh[HRP * 768],  g_w1rl[HRP * 768];

__device__ __forceinline__ float elu_f(float x) {
    return x > 0.f ? x : (__expf(x) - 1.f);
}
static __device__ __forceinline__ uint32_t pack2(float a, float b) {
    __nv_bfloat162 h = __floats2bfloat162_rn(a, b);
    return *reinterpret_cast<uint32_t*>(&h);
}
static __device__ __forceinline__ uint32_t smem_addr(const void* p) {
    uint32_t a;
    asm("{ .reg .u64 t; cvta.to.shared.u64 t, %1; cvt.u32.u64 %0, t; }" : "=r"(a) : "l"(p));
    return a;
}
static __device__ __forceinline__ void mma16816(float* c, const uint32_t* a,
                                                const uint32_t* b) {
    asm volatile(
        "mma.sync.aligned.m16n8k16.row.col.f32.bf16.bf16.f32 "
        "{%0,%1,%2,%3}, {%4,%5,%6,%7}, {%8,%9}, {%0,%1,%2,%3};"
        : "+f"(c[0]), "+f"(c[1]), "+f"(c[2]), "+f"(c[3])
        : "r"(a[0]), "r"(a[1]), "r"(a[2]), "r"(a[3]), "r"(b[0]), "r"(b[1]));
}
static __device__ __forceinline__ void ldsm4(uint32_t* r, uint32_t addr) {
    asm volatile("ldmatrix.sync.aligned.m8n8.x4.shared.b16 {%0,%1,%2,%3}, [%4];"
        : "=r"(r[0]), "=r"(r[1]), "=r"(r[2]), "=r"(r[3]) : "r"(addr));
}
static __device__ __forceinline__ void ldsm2(uint32_t* r, uint32_t addr) {
    asm volatile("ldmatrix.sync.aligned.m8n8.x2.shared.b16 {%0,%1}, [%2];"
        : "=r"(r[0]), "=r"(r[1]) : "r"(addr));
}
static __device__ __forceinline__ void cpa16(uint32_t d, const void* s) {
    asm volatile("cp.async.ca.shared.global [%0], [%1], 16;" :: "r"(d), "l"(s));
}

#define KPAD    80   // bytes per k-row (40 bf16)
#define BUF_SZ  61440
#define AH_OFF  0
#define AL_OFF  10240
#define BH_OFF  20480
#define BL_OFF  40960

// ldmatrix lane-address components
#define LDSM_A_ROW(lane)  (((lane) & 7) + ((((lane) >> 3) & 1) << 3))
#define LDSM_A_KOFF(lane) ((((lane) >> 4) & 1) * 16)
#define LDSM_B_ROW(lane)  ((lane) & 7)
#define LDSM_B_KOFF(lane) ((((lane) >> 3) & 1) * 16)

// stage one chunk (A: 128x32, B: 256x32, hi+lo) into buffer bufb, commit group
#define STAGE_CHUNK(bufb, pAH, pAL, k0, BHsrc, BLsrc, nbase, SRCK)              \
    do {                                                                        \
        cpa16((bufb) + AH_OFF + mrow * KPAD + kq8 * 2, (pAH) + (k0));           \
        cpa16((bufb) + AL_OFF + mrow * KPAD + kq8 * 2, (pAL) + (k0));           \
        _Pragma("unroll")                                                       \
        for (int it_ = 0; it_ < 2; it_++) {                                     \
            int idx_ = t + it_ * 512;                                           \
            int n_ = idx_ >> 2, seg_ = idx_ & 3;                                \
            size_t so_ = (size_t)((nbase) + n_) * (SRCK) + (k0) + seg_ * 8;     \
            cpa16((bufb) + BH_OFF + n_ * KPAD + seg_ * 16, (BHsrc) + so_);      \
            cpa16((bufb) + BL_OFF + n_ * KPAD + seg_ * 16, (BLsrc) + so_);      \
        }                                                                       \
        asm volatile("cp.async.commit_group;");                                 \
    } while (0)

// One k-step of the 3-product split GEMM
#define SPLIT_MMA_KSTEP(aBH, aBL, bBH, bBL, ksb, acc)                          \
    do {                                                                       \
        uint32_t af[4][4], bh[4][2], bl[4][2];                                 \
        _Pragma("unroll")                                                      \
        for (int tm = 0; tm < 4; tm++) ldsm4(af[tm], (aBH) + tm * 16 * KPAD + (ksb)); \
        _Pragma("unroll")                                                      \
        for (int tn = 0; tn < 4; tn++) ldsm2(bh[tn], (bBH) + tn * 8 * KPAD + (ksb)); \
        _Pragma("unroll")                                                      \
        for (int tn = 0; tn < 4; tn++) ldsm2(bl[tn], (bBL) + tn * 8 * KPAD + (ksb)); \
        _Pragma("unroll")                                                      \
        for (int tm = 0; tm < 4; tm++)                                         \
            _Pragma("unroll")                                                  \
            for (int tn = 0; tn < 4; tn++)                                     \
                mma16816(acc[tm][tn], af[tm], bh[tn]);                         \
        _Pragma("unroll")                                                      \
        for (int tm = 0; tm < 4; tm++)                                         \
            _Pragma("unroll")                                                  \
            for (int tn = 0; tn < 4; tn++)                                     \
                mma16816(acc[tm][tn], af[tm], bl[tn]);                         \
        _Pragma("unroll")                                                      \
        for (int tm = 0; tm < 4; tm++) ldsm4(af[tm], (aBL) + tm * 16 * KPAD + (ksb)); \
        _Pragma("unroll")                                                      \
        for (int tm = 0; tm < 4; tm++)                                         \
            _Pragma("unroll")                                                  \
            for (int tn = 0; tn < 4; tn++)                                     \
                mma16816(acc[tm][tn], af[tm], bh[tn]);                         \
    } while (0)

// ---------------- weight pack kernels ---------------------------------------
__global__ void k_pack_uv(const float* __restrict__ W1t) {
    int idx = blockIdx.x * 256 + threadIdx.x;
    int n = idx / 768, k = idx - n * 768;
    int isV = (n >= 1536);
    int col = isV ? n - 1536 : n;
    float v = W1t[(size_t)((isV ? 770 : 2) + k) * HT + col];
    __nv_bfloat16 h = __float2bfloat16(v);
    g_wuvh[idx] = h;
    g_wuvl[idx] = __float2bfloat16(v - __bfloat162float(h));
}
__global__ void k_pack_w2(const float* __restrict__ W2t) {
    int idx = blockIdx.x * 256 + threadIdx.x;
    int n = idx / 1536, k = idx - n * 1536;
    float v = W2t[(size_t)k * 768 + n];
    __nv_bfloat16 h = __float2bfloat16(v);
    g_w2h[idx] = h;
    g_w2l[idx] = __float2bfloat16(v - __bfloat162float(h));
}
__global__ void k_pack_w1r(const float* __restrict__ W1r) {
    int idx = blockIdx.x * 256 + threadIdx.x;
    int n = idx / 768, k = idx - n * 768;
    float v = (n < HR) ? W1r[(size_t)(2 + k) * HR + n] : 0.f;
    __nv_bfloat16 h = __float2bfloat16(v);
    g_w1rh[idx] = h;
    g_w1rl[idx] = __float2bfloat16(v - __bfloat162float(h));
}

// ---------------- kernel 0: triangle rank -> edge table ---------------------
__global__ void k_trimap() {
    int e = blockIdx.x * 1024 + threadIdx.x;
    int b = e >> 12, i = (e >> 6) & 63, j = e & 63;
    if (i <= j) {
        int rank = b * TRI_B + i * (129 - i) / 2 + (j - i);
        g_tri[rank] = e;
    }
}

// ---------------- kernel 1: agg --------------------------------------------
__global__ void k_agg(const float* __restrict__ x, const float* __restrict__ adjs,
                      const float* __restrict__ flags) {
    int bi = blockIdx.x;
    int b = bi >> 6, i = bi & 63;
    int f = threadIdx.x;
    __shared__ float a0s[64], a1s[64];
    float fi = flags[b * 64 + i];
    if (threadIdx.x < 64) {
        int j = threadIdx.x;
        float fj = flags[b * 64 + j];
        float a = adjs[(size_t)bi * 64 + j];
        float m = fi * fj;
        a0s[j] = a * m;
        a1s[j] = (1.f - a) * m;
    }
    __syncthreads();
    float s0 = 0.f, s1 = 0.f;
    const float* xb = x + (size_t)b * NNODE * FIN;
    #pragma unroll 4
    for (int j = 0; j < 64; j++) {
        float xv = xb[j * FIN + f];
        s0 += a0s[j] * xv;
        s1 += a1s[j] * xv;
    }
    g_agg[bi * 256 + f] = s0;
    g_agg[bi * 256 + 128 + f] = s1;
}

// ---------------- kernel 2: GIN MLPs -> x_o (+ bf16 hi/lo split) ------------
__global__ void k_gin(const float* __restrict__ x, const float* __restrict__ flags,
                      const float* __restrict__ Wg, const float* __restrict__ bg,
                      const float* __restrict__ Wout, const float* __restrict__ bout,
                      float* __restrict__ out_xo) {
    __shared__ float aggs[8][256];
    __shared__ float xs[8][128];
    __shared__ float hs[8][256];
    __shared__ float fl[8];
    int r0 = blockIdx.x * 8;
    int t = threadIdx.x;
    for (int idx = t; idx < 8 * 256; idx += 256)
        aggs[idx >> 8][idx & 255] = g_agg[r0 * 256 + idx];
    for (int idx = t; idx < 8 * 128; idx += 256)
        xs[idx >> 7][idx & 127] = x[(size_t)r0 * 128 + idx];
    if (t < 8) fl[t] = flags[r0 + t];
    __syncthreads();
    {
        float acc[8];
        float bgv = bg[t];
        #pragma unroll
        for (int r = 0; r < 8; r++) acc[r] = bgv;
        for (int k = 0; k < 256; k++) {
            float w = Wg[k * 256 + t];
            #pragma unroll
            for (int r = 0; r < 8; r++) acc[r] += aggs[r][k] * w;
        }
        #pragma unroll
        for (int r = 0; r < 8; r++) hs[r][t] = elu_f(acc[r]) * fl[r];
    }
    __syncthreads();
    float acc[3][8];
    #pragma unroll
    for (int c = 0; c < 3; c++) {
        float bo = bout[t + c * 256];
        #pragma unroll
        for (int r = 0; r < 8; r++) acc[c][r] = bo;
    }
    for (int k = 0; k < 128; k++) {
        float o[8];
        #pragma unroll
        for (int r = 0; r < 8; r++) o[r] = xs[r][k];
        #pragma unroll
        for (int c = 0; c < 3; c++) {
            float w = Wout[k * 768 + t + c * 256];
            #pragma unroll
            for (int r = 0; r < 8; r++) acc[c][r] += o[r] * w;
        }
    }
    for (int k = 0; k < 256; k++) {
        float o[8];
        #pragma unroll
        for (int r = 0; r < 8; r++) o[r] = hs[r][k];
        #pragma unroll
        for (int c = 0; c < 3; c++) {
            float w = Wout[(128 + k) * 768 + t + c * 256];
            #pragma unroll
            for (int r = 0; r < 8; r++) acc[c][r] += o[r] * w;
        }
    }
    #pragma unroll
    for (int c = 0; c < 3; c++)
        #pragma unroll
        for (int r = 0; r < 8; r++) {
            size_t idx = (size_t)(r0 + r) * 768 + t + c * 256;
            float val = tanhf(acc[c][r]) * fl[r];
            out_xo[idx] = val;
            __nv_bfloat16 h = __float2bfloat16(val);
            g_xh[idx] = h;
            g_xl[idx] = __float2bfloat16(val - __bfloat162float(h));
        }
}

// ---------------- kernel 3: U,V via 2-stage pipelined mma (R13) --------------
#define UV_SMEM (2 * BUF_SZ)

__global__ void __launch_bounds__(512, 1)
k_uv_mma() {
    extern __shared__ char sm[];
    uint32_t sb = smem_addr(sm);
    int t = threadIdx.x;
    int m0 = blockIdx.y * 128;
    int ng0 = blockIdx.x * 256;
    const int isU = (ng0 < HT);

    int wid = t >> 5, lane = t & 31;
    int mw = (wid & 1) * 64, nw = (wid >> 1) * 32;
    int row4 = lane >> 2, quad = lane & 3;
    int mrow = t >> 2, kq8 = (t & 3) * 8;
    const __nv_bfloat16* pAH = g_xh + (size_t)(m0 + mrow) * 768 + kq8;
    const __nv_bfloat16* pAL = g_xl + (size_t)(m0 + mrow) * 768 + kq8;
    int laneA = (mw + LDSM_A_ROW(lane)) * KPAD + LDSM_A_KOFF(lane);
    int laneB = (nw + LDSM_B_ROW(lane)) * KPAD + LDSM_B_KOFF(lane);

    float acc[4][4][4];
    #pragma unroll
    for (int tm = 0; tm < 4; tm++)
        #pragma unroll
        for (int tn = 0; tn < 4; tn++)
            #pragma unroll
            for (int q = 0; q < 4; q++) acc[tm][tn][q] = 0.f;

    STAGE_CHUNK(sb, pAH, pAL, 0, g_wuvh, g_wuvl, ng0, 768);
    for (int c = 0; c < 24; c++) {
        uint32_t cur = sb + (c & 1) * BUF_SZ;
        uint32_t nxt = sb + ((c + 1) & 1) * BUF_SZ;
        __syncthreads();
        if (c + 1 < 24) {
            STAGE_CHUNK(nxt, pAH, pAL, (c + 1) * 32, g_wuvh, g_wuvl, ng0, 768);
            asm volatile("cp.async.wait_group 1;" ::: "memory");
        } else {
            asm volatile("cp.async.wait_group 0;" ::: "memory");
        }
        __syncthreads();
        #pragma unroll
        for (int ks = 0; ks < 2; ks++)
            SPLIT_MMA_KSTEP(cur + AH_OFF + laneA, cur + AL_OFF + laneA,
                            cur + BH_OFF + laneB, cur + BL_OFF + laneB, ks * 32, acc);
    }

    float* Obase = (isU ? g_U : g_V);
    int c0 = isU ? ng0 : ng0 - HT;
    #pragma unroll
    for (int tm = 0; tm < 4; tm++) {
        int gr = m0 + mw + tm * 16 + row4;
        #pragma unroll
        for (int tn = 0; tn < 4; tn++) {
            int gc = c0 + nw + tn * 8 + quad * 2;
            float* p0 = Obase + (size_t)gr * HT + gc;
            float* p1 = Obase + (size_t)(gr + 8) * HT + gc;
            *(float2*)p0 = make_float2(acc[tm][tn][0], acc[tm][tn][1]);
            *(float2*)p1 = make_float2(acc[tm][tn][2], acc[tm][tn][3]);
        }
    }
}

// ---------------- kernel 4a: adjacency sums (parallel, SMEM-tiled) ----------
__global__ void k_statA(const float* __restrict__ adjs, const float* __restrict__ flags) {
    __shared__ float a[64][65];
    __shared__ float fl[64];
    __shared__ float red[64];
    int b = blockIdx.x;    // 16 blocks
    int i = threadIdx.x;   // 64 threads
    for (int idx = i; idx < 4096; idx += 64)
        a[idx >> 6][idx & 63] = adjs[(size_t)b * 4096 + idx];
    fl[i] = flags[b * 64 + i];
    __syncthreads();
    float fi = fl[i];
    float r0 = 0.f, r1 = 0.f, c0 = 0.f, c1 = 0.f;
    float s0 = 0.f, s1 = 0.f, s00 = 0.f, s01 = 0.f, s11 = 0.f;
    #pragma unroll 4
    for (int j = 0; j < 64; j++) {
        float m = fi * fl[j];
        float av = a[i][j];
        float a0 = av * m, a1 = (1.f - av) * m;
        r0 += a0; r1 += a1;
        s0 += a0; s1 += a1;
        s00 += a0 * a0; s01 += a0 * a1; s11 += a1 * a1;
        float at = a[j][i];
        c0 += at * m; c1 += (1.f - at) * m;
    }
    int bi = b * 64 + i;
    g_r0[bi] = r0; g_r1[bi] = r1; g_c0s[bi] = c0; g_c1s[bi] = c1;
    float vals[5] = {s0, s1, s00, s01, s11};
    for (int v = 0; v < 5; v++) {
        red[i] = vals[v];
        __syncthreads();
        for (int off = 32; off > 0; off >>= 1) {
            if (i < off) red[i] += red[i + off];
            __syncthreads();
        }
        if (i == 0) g_scp[b * 5 + v] = red[0];
        __syncthreads();
    }
}

// ---------------- kernel 4b: per-(batch,k) partials --------------------------
__global__ void k_statB() {
    int k = blockIdx.x * 128 + threadIdx.x;   // 12 x 128 -> 1536
    int b = blockIdx.y;                       // 16
    float ub = 0.f, vb = 0.f, u2 = 0.f, v2 = 0.f, T0 = 0.f, T1 = 0.f;
    #pragma unroll 4
    for (int r = 0; r < 64; r++) {
        int bi = b * 64 + r;
        float u = g_U[(size_t)bi * HT + k];
        float v = g_V[(size_t)bi * HT + k];
        ub += u; vb += v; u2 += u * u; v2 += v * v;
        T0 += u * g_r0[bi] + v * g_c0s[bi];
        T1 += u * g_r1[bi] + v * g_c1s[bi];
    }
    g_part[0 * 16 * HT + b * HT + k] = 64.f * (ub + vb);
    g_part[1 * 16 * HT + b * HT + k] = 64.f * (u2 + v2) + 2.f * ub * vb;
    g_part[2 * 16 * HT + b * HT + k] = T0;
    g_part[3 * 16 * HT + b * HT + k] = T1;
}

// ---------------- kernel 4c: finalize BN constants ---------------------------
__global__ void k_statC(const float* __restrict__ W1t, const float* __restrict__ b1t,
                        const float* __restrict__ gamma, const float* __restrict__ beta) {
    int k = blockIdx.x * 256 + threadIdx.x;   // 6 x 256
    float w0 = W1t[k], w1 = W1t[HT + k];
    float sumz = 0.f, sqb = 0.f, T0 = 0.f, T1 = 0.f;
    float S0 = 0.f, S1 = 0.f, S00 = 0.f, S01 = 0.f, S11 = 0.f;
    for (int b = 0; b < 16; b++) {
        sumz += g_part[0 * 16 * HT + b * HT + k];
        sqb  += g_part[1 * 16 * HT + b * HT + k];
        T0   += g_part[2 * 16 * HT + b * HT + k];
        T1   += g_part[3 * 16 * HT + b * HT + k];
        S0 += g_scp[b * 5 + 0]; S1 += g_scp[b * 5 + 1];
        S00 += g_scp[b * 5 + 2]; S01 += g_scp[b * 5 + 3]; S11 += g_scp[b * 5 + 4];
    }
    float sz = sumz + S0 * w0 + S1 * w1;
    float sq = sqb + 2.f * (w0 * T0 + w1 * T1)
             + S00 * w0 * w0 + 2.f * S01 * w0 * w1 + S11 * w1 * w1;
    const float inv = 1.f / 65536.f;
    float mu_z = sz * inv;
    float var = fmaxf(sq * inv - mu_z * mu_z, 0.f);
    float mu = mu_z + b1t[k];
    float c1 = gamma[k] * rsqrtf(var + 1e-5f);
    g_c1[k] = c1;
    g_c2[k] = beta[k] - mu * c1;
}

// ---------------- kernel 5b: h2sum on triangle (balanced pairs) -------------
__global__ void __launch_bounds__(384)
k_agen_tri(const float* __restrict__ adjs, const float* __restrict__ flags,
           const float* __restrict__ W1t) {
    int blk = blockIdx.x;
    int b = blk >> 5, p = blk & 31;
    int c4 = threadIdx.x * 4;
    float4 w0 = __ldg((const float4*)(W1t + c4));
    float4 w1 = __ldg((const float4*)(W1t + HT + c4));
    float4 c1 = *(const float4*)(g_c1 + c4);
    float4 c2 = *(const float4*)(g_c2 + c4);
    #pragma unroll
    for (int half = 0; half < 2; half++) {
        int i = half ? (63 - p) : p;
        int bi = b * 64 + i;
        float4 ui = *(const float4*)(g_U + (size_t)bi * HT + c4);
        float4 vi = *(const float4*)(g_V + (size_t)bi * HT + c4);
        float fi = __ldg(flags + b * 64 + i);
        size_t rank0 = (size_t)b * TRI_B + i * (129 - i) / 2;
        for (int j = i; j < 64; j++) {
            float fj = __ldg(flags + b * 64 + j);
            float mk = fi * fj;
            float aij = __ldg(adjs + (size_t)b * 4096 + i * 64 + j);
            float aji = __ldg(adjs + (size_t)b * 4096 + j * 64 + i);
            float a0ij = aij * mk, a1ij = (1.f - aij) * mk;
            float a0ji = aji * mk, a1ji = (1.f - aji) * mk;
            float4 uj = *(const float4*)(g_U + (size_t)(b * 64 + j) * HT + c4);
            float4 vj = *(const float4*)(g_V + (size_t)(b * 64 + j) * HT + c4);
            float s0 = elu_f((ui.x + vj.x + a0ij * w0.x + a1ij * w1.x) * c1.x + c2.x)
                     + elu_f((uj.x + vi.x + a0ji * w0.x + a1ji * w1.x) * c1.x + c2.x);
            float s1 = elu_f((ui.y + vj.y + a0ij * w0.y + a1ij * w1.y) * c1.y + c2.y)
                     + elu_f((uj.y + vi.y + a0ji * w0.y + a1ji * w1.y) * c1.y + c2.y);
            float s2 = elu_f((ui.z + vj.z + a0ij * w0.z + a1ij * w1.z) * c1.z + c2.z)
                     + elu_f((uj.z + vi.z + a0ji * w0.z + a1ji * w1.z) * c1.z + c2.z);
            float s3 = elu_f((ui.w + vj.w + a0ij * w0.w + a1ij * w1.w) * c1.w + c2.w)
                     + elu_f((uj.w + vi.w + a0ji * w0.w + a1ji * w1.w) * c1.w + c2.w);
            float r0 = s0 - __bfloat162float(__float2bfloat16(s0));
            float r1 = s1 - __bfloat162float(__float2bfloat16(s1));
            float r2 = s2 - __bfloat162float(__float2bfloat16(s2));
            float r3 = s3 - __bfloat162float(__float2bfloat16(s3));
            size_t row = (rank0 + (j - i)) * HT + c4;
            *(uint2*)(g_hh + row) = make_uint2(pack2(s0, s1), pack2(s2, s3));
            *(uint2*)(g_hl + row) = make_uint2(pack2(r0, r1), pack2(r2, r3));
        }
    }
}

// ---------------- kernel 6: triangle translate GEMM -> S (R13) ---------------
#define GP_MKS  (2 * BUF_SZ)
#define GP_SMEM (2 * BUF_SZ + 512)

__global__ void __launch_bounds__(512, 1)
k_gemm2_tri(const float* __restrict__ flags, const float* __restrict__ b2t) {
    extern __shared__ char sm[];
    uint32_t sb = smem_addr(sm);
    float* mks = (float*)(sm + GP_MKS);
    int t = threadIdx.x;
    int m0 = blockIdx.y * 128, n0g = blockIdx.x * 256;

    if (t < 128) {
        int e = __ldg(g_tri + m0 + t);
        int b = e >> 12, i = (e >> 6) & 63, j = e & 63;
        mks[t] = __ldg(flags + b * 64 + i) * __ldg(flags + b * 64 + j);
    }

    int wid = t >> 5, lane = t & 31;
    int mw = (wid & 1) * 64, nw = (wid >> 1) * 32;
    int row4 = lane >> 2, quad = lane & 3;
    int mrow = t >> 2, kq8 = (t & 3) * 8;
    const __nv_bfloat16* pAH = g_hh + (size_t)(m0 + mrow) * HT + kq8;
    const __nv_bfloat16* pAL = g_hl + (size_t)(m0 + mrow) * HT + kq8;
    int laneA = (mw + LDSM_A_ROW(lane)) * KPAD + LDSM_A_KOFF(lane);
    int laneB = (nw + LDSM_B_ROW(lane)) * KPAD + LDSM_B_KOFF(lane);

    float acc[4][4][4];
    #pragma unroll
    for (int tm = 0; tm < 4; tm++)
        #pragma unroll
        for (int tn = 0; tn < 4; tn++)
            #pragma unroll
            for (int q = 0; q < 4; q++) acc[tm][tn][q] = 0.f;

    STAGE_CHUNK(sb, pAH, pAL, 0, g_w2h, g_w2l, n0g, 1536);
    for (int c = 0; c < 48; c++) {
        uint32_t cur = sb + (c & 1) * BUF_SZ;
        uint32_t nxt = sb + ((c + 1) & 1) * BUF_SZ;
        __syncthreads();
        if (c + 1 < 48) {
            STAGE_CHUNK(nxt, pAH, pAL, (c + 1) * 32, g_w2h, g_w2l, n0g, 1536);
            asm volatile("cp.async.wait_group 1;" ::: "memory");
        } else {
            asm volatile("cp.async.wait_group 0;" ::: "memory");
        }
        __syncthreads();
        #pragma unroll
        for (int ks = 0; ks < 2; ks++)
            SPLIT_MMA_KSTEP(cur + AH_OFF + laneA, cur + AL_OFF + laneA,
                            cur + BH_OFF + laneB, cur + BL_OFF + laneB, ks * 32, acc);
    }

    #pragma unroll
    for (int tm = 0; tm < 4; tm++) {
        int r0 = mw + tm * 16 + row4;
        float mk0 = mks[r0], mk1 = mks[r0 + 8];
        size_t gr0 = (size_t)(m0 + r0) * 768;
        size_t gr1 = (size_t)(m0 + r0 + 8) * 768;
        #pragma unroll
        for (int tn = 0; tn < 4; tn++) {
            int gc = n0g + nw + tn * 8 + quad * 2;
            float bx = 2.f * __ldg(b2t + gc), by = 2.f * __ldg(b2t + gc + 1);
            float s00 = (acc[tm][tn][0] + bx) * mk0, s01 = (acc[tm][tn][1] + by) * mk0;
            float s10 = (acc[tm][tn][2] + bx) * mk1, s11 = (acc[tm][tn][3] + by) * mk1;
            float r00 = s00 - __bfloat162float(__float2bfloat16(s00));
            float r01 = s01 - __bfloat162float(__float2bfloat16(s01));
            float r10 = s10 - __bfloat162float(__float2bfloat16(s10));
            float r11 = s11 - __bfloat162float(__float2bfloat16(s11));
            *(uint32_t*)(g_ssh + gr0 + gc) = pack2(s00, s01);
            *(uint32_t*)(g_ssl + gr0 + gc) = pack2(r00, r01);
            *(uint32_t*)(g_ssh + gr1 + gc) = pack2(s10, s11);
            *(uint32_t*)(g_ssl + gr1 + gc) = pack2(r10, r11);
        }
    }
}

// ---------------- kernel 7: triangle final_read_score (R13) -----------------
#define ST_A0IJ (2 * BUF_SZ)
#define ST_A1IJ (2 * BUF_SZ + 512)
#define ST_A0JI (2 * BUF_SZ + 1024)
#define ST_A1JI (2 * BUF_SZ + 1536)
#define ST_ESM  (2 * BUF_SZ + 2048)
#define ST_RED  (2 * BUF_SZ + 2560)
#define ST_SMEM (2 * BUF_SZ + 2560 + 8192)

__global__ void __launch_bounds__(512, 1)
k_score_tri(const float* __restrict__ adjs, const float* __restrict__ flags,
            const float* __restrict__ W1r, const float* __restrict__ b1r,
            const float* __restrict__ W2r, const float* __restrict__ b2r,
            float* __restrict__ out_score) {
    extern __shared__ char sm[];
    uint32_t sb = smem_addr(sm);
    float* a0ijs = (float*)(sm + ST_A0IJ);
    float* a1ijs = (float*)(sm + ST_A1IJ);
    float* a0jis = (float*)(sm + ST_A0JI);
    float* a1jis = (float*)(sm + ST_A1JI);
    int*   esm   = (int*)(sm + ST_ESM);
    float* red   = (float*)(sm + ST_RED);
    int t = threadIdx.x;
    int m0 = blockIdx.x * 128;

    if (t < 128) {
        int e = __ldg(g_tri + m0 + t);
        esm[t] = e;
        int b = e >> 12, i = (e >> 6) & 63, j = e & 63;
        float mk = __ldg(flags + b * 64 + i) * __ldg(flags + b * 64 + j);
        float aij = __ldg(adjs + e);
        float aji = __ldg(adjs + (b << 12) + (j << 6) + i);
        a0ijs[t] = aij * mk; a1ijs[t] = (1.f - aij) * mk;
        a0jis[t] = aji * mk; a1jis[t] = (1.f - aji) * mk;
    }

    int wid = t >> 5, lane = t & 31;
    int mw = (wid & 1) * 64, nw = (wid >> 1) * 32;
    int row4 = lane >> 2, quad = lane & 3;
    int mrow = t >> 2, kq8 = (t & 3) * 8;
    const __nv_bfloat16* pSH = g_ssh + (size_t)(m0 + mrow) * 768 + kq8;
    const __nv_bfloat16* pSL = g_ssl + (size_t)(m0 + mrow) * 768 + kq8;
    int laneA = (mw + LDSM_A_ROW(lane)) * KPAD + LDSM_A_KOFF(lane);
    int laneB = (nw + LDSM_B_ROW(lane)) * KPAD + LDSM_B_KOFF(lane);

    float sij[4][2], sji[4][2];
    #pragma unroll
    for (int tm = 0; tm < 4; tm++) {
        sij[tm][0] = 0.f; sij[tm][1] = 0.f;
        sji[tm][0] = 0.f; sji[tm][1] = 0.f;
    }
    __syncthreads();

    STAGE_CHUNK(sb, pSH, pSL, 0, g_w1rh, g_w1rl, 0, 768);
    for (int nc = 0; nc < 7; nc++) {
        int n0 = nc * 256;
        float acc[4][4][4];
        #pragma unroll
        for (int tn = 0; tn < 4; tn++)
            #pragma unroll
            for (int cq = 0; cq < 2; cq++) {
                int n = n0 + nw + tn * 8 + quad * 2 + cq;
                float br = (n < HR) ? __ldg(b1r + n) : 0.f;
                #pragma unroll
                for (int tm = 0; tm < 4; tm++) {
                    acc[tm][tn][cq] = br;
                    acc[tm][tn][2 + cq] = br;
                }
            }
        for (int c = 0; c < 24; c++) {
            uint32_t cur = sb + (c & 1) * BUF_SZ;
            uint32_t nxt = sb + ((c + 1) & 1) * BUF_SZ;
            __syncthreads();
            if (c + 1 < 24) {
                STAGE_CHUNK(nxt, pSH, pSL, (c + 1) * 32, g_w1rh, g_w1rl, n0, 768);
                asm volatile("cp.async.wait_group 1;" ::: "memory");
            } else {
                asm volatile("cp.async.wait_group 0;" ::: "memory");
            }
            __syncthreads();
            #pragma unroll
            for (int ks = 0; ks < 2; ks++)
                SPLIT_MMA_KSTEP(cur + AH_OFF + laneA, cur + AL_OFF + laneA,
                                cur + BH_OFF + laneB, cur + BL_OFF + laneB, ks * 32, acc);
        }
        // prefetch next nc's chunk 0 (buffer 0 free) before epilogue
        if (nc + 1 < 7)
            STAGE_CHUNK(sb, pSH, pSL, 0, g_w1rh, g_w1rl, (nc + 1) * 256, 768);
        // epilogue: elu both orientations, dot with W2r
        #pragma unroll
        for (int tn = 0; tn < 4; tn++)
            #pragma unroll
            for (int cq = 0; cq < 2; cq++) {
                int n = n0 + nw + tn * 8 + quad * 2 + cq;
                bool ok = n < HR;
                float w0 = ok ? __ldg(W1r + n) : 0.f;
                float w1 = ok ? __ldg(W1r + HR + n) : 0.f;
                float w2 = ok ? __ldg(W2r + n) : 0.f;
                #pragma unroll
                for (int tm = 0; tm < 4; tm++) {
                    int r0 = mw + tm * 16 + row4;
                    float g0 = acc[tm][tn][cq], g1 = acc[tm][tn][2 + cq];
                    sij[tm][0] += elu_f(g0 + a0ijs[r0] * w0 + a1ijs[r0] * w1) * w2;
                    sji[tm][0] += elu_f(g0 + a0jis[r0] * w0 + a1jis[r0] * w1) * w2;
                    sij[tm][1] += elu_f(g1 + a0ijs[r0 + 8] * w0 + a1ijs[r0 + 8] * w1) * w2;
                    sji[tm][1] += elu_f(g1 + a0jis[r0 + 8] * w0 + a1jis[r0 + 8] * w1) * w2;
                }
            }
    }
    #pragma unroll
    for (int off = 1; off <= 2; off <<= 1)
        #pragma unroll
        for (int tm = 0; tm < 4; tm++) {
            sij[tm][0] += __shfl_xor_sync(0xffffffffu, sij[tm][0], off);
            sij[tm][1] += __shfl_xor_sync(0xffffffffu, sij[tm][1], off);
            sji[tm][0] += __shfl_xor_sync(0xffffffffu, sji[tm][0], off);
            sji[tm][1] += __shfl_xor_sync(0xffffffffu, sji[tm][1], off);
        }
    __syncthreads();
    if (quad == 0) {
        int wn = wid >> 1;
        #pragma unroll
        for (int tm = 0; tm < 4; tm++) {
            int r0 = mw + tm * 16 + row4;
            red[r0 * 8 + wn] = sij[tm][0];
            red[(r0 + 8) * 8 + wn] = sij[tm][1];
            red[1024 + r0 * 8 + wn] = sji[tm][0];
            red[1024 + (r0 + 8) * 8 + wn] = sji[tm][1];
        }
    }
    __syncthreads();
    if (t < 128) {
        float s1 = 0.f, s2 = 0.f;
        #pragma unroll
        for (int w8 = 0; w8 < 8; w8++) {
            s1 += red[t * 8 + w8];
            s2 += red[1024 + t * 8 + w8];
        }
        int e = esm[t];
        int b = e >> 12, i = (e >> 6) & 63, j = e & 63;
        float b2 = b2r[0];
        out_score[e] = (i == j) ? 0.f : (s1 + b2);
        if (i != j)
            out_score[(b << 12) + (j << 6) + i] = s2 + b2;
    }
}

// ---------------- launch -----------------------------------------------------
extern "C" void kernel_launch(void* const* d_in, const int* in_sizes, int n_in,
                              void* d_out, int out_size) {
    const float* x     = (const float*)d_in[0];
    const float* adjs  = (const float*)d_in[1];
    const float* flags = (const float*)d_in[2];
    const float* Wg    = (const float*)d_in[3];
    const float* bg    = (const float*)d_in[4];
    const float* Wout  = (const float*)d_in[5];
    const float* bout  = (const float*)d_in[6];
    const float* W1t   = (const float*)d_in[7];
    const float* b1t   = (const float*)d_in[8];
    const float* gamma = (const float*)d_in[9];
    const float* beta  = (const float*)d_in[10];
    const float* W2t   = (const float*)d_in[11];
    const float* b2t   = (const float*)d_in[12];
    const float* W1r   = (const float*)d_in[13];
    const float* b1r   = (const float*)d_in[14];
    const float* W2r   = (const float*)d_in[15];
    const float* b2r   = (const float*)d_in[16];

    float* out_score = (float*)d_out;             // [B,N,N] = 65536
    float* out_xo    = (float*)d_out + NEDGE;     // [B,N,768]

    cudaFuncSetAttribute(k_uv_mma, cudaFuncAttributeMaxDynamicSharedMemorySize, UV_SMEM);
    cudaFuncSetAttribute(k_gemm2_tri, cudaFuncAttributeMaxDynamicSharedMemorySize, GP_SMEM);
    cudaFuncSetAttribute(k_score_tri, cudaFuncAttributeMaxDynamicSharedMemorySize, ST_SMEM);

    k_pack_uv<<<3072 * 768 / 256, 256>>>(W1t);
    k_pack_w2<<<768 * 1536 / 256, 256>>>(W2t);
    k_pack_w1r<<<HRP * 768 / 256, 256>>>(W1r);
    k_trimap<<<64, 1024>>>();
    k_statA<<<16, 64>>>(adjs, flags);
    k_agg<<<NROW, 128>>>(x, adjs, flags);
    k_gin<<<NROW / 8, 256>>>(x, flags, Wg, bg, Wout, bout, out_xo);
    k_uv_mma<<<dim3(12, 8), 512, UV_SMEM>>>();
    k_statB<<<dim3(12, 16), 128>>>();
    k_statC<<<6, 256>>>(W1t, b1t, gamma, beta);
    k_agen_tri<<<512, 384>>>(adjs, flags, W1t);
    k_gemm2_tri<<<dim3(3, 260), 512, GP_SMEM>>>(flags, b2t);
    k_score_tri<<<260, 512, ST_SMEM>>>(adjs, flags, W1r, b1r, W2r, b2r, out_score);
}

// round 17
// speedup vs baseline: 1.1407x; 1.0278x over previous
#include <cuda_runtime.h>
#include <cuda_bf16.h>
#include <stdint.h>
#include <cstdint>
#include <math.h>

// Problem constants
#define BB      16
#define NNODE   64
#define FIN     128
#define FHID    256
#define ODIM    768
#define HT      1536   // translate hidden
#define DR      770
#define HR      1540
#define NEDGE   65536  // B*N*N
#define NROW    1024   // B*N
#define TRI_B   2080   // 64*65/2 per batch
#define TRI_TOT 33280  // 16 * TRI_B (= 260 * 128)
#define HRP     1792   // W1r n-padding (14*128)

// ---------------- scratch (device globals; no runtime allocation) ----------
__device__ float g_agg[NROW * 256];
__device__ float g_U[NROW * HT];
__device__ float g_V[NROW * HT];
__device__ float g_part[4 * 16 * HT];   // SoA stats partials [v][b][k]
__device__ float g_scp[16 * 5];         // per-batch scalar partials
__device__ __align__(16) float g_c1[HT];
__device__ __align__(16) float g_c2[HT];
__device__ float g_r0[NROW], g_r1[NROW], g_c0s[NROW], g_c1s[NROW];
__device__ int   g_tri[TRI_TOT];
__device__ __align__(16) __nv_bfloat16 g_xh[NROW * ODIM];
__device__ __align__(16) __nv_bfloat16 g_xl[NROW * ODIM];
__device__ __align__(16) __nv_bfloat16 g_hh[(size_t)TRI_TOT * HT];
__device__ __align__(16) __nv_bfloat16 g_hl[(size_t)TRI_TOT * HT];
__device__ __align__(16) __nv_bfloat16 g_ssh[(size_t)TRI_TOT * ODIM];
__device__ __align__(16) __nv_bfloat16 g_ssl[(size_t)TRI_TOT * ODIM];
// pre-packed B weights, [n][k] bf16 hi/lo
__device__ __align__(16) __nv_bfloat16 g_wuvh[3072 * 768], g_wuvl[3072 * 768];
__device__ __align__(16) __nv_bfloat16 g_w2h[768 * 1536],  g_w2l[768 * 1536];
__device__ __align__(16) __nv_bfloat16 g_w1rh[HRP * 768],  g_w1rl[HRP * 768];

__device__ __forceinline__ float elu_f(float x) {
    return x > 0.f ? x : (__expf(x) - 1.f);
}
static __device__ __forceinline__ uint32_t pack2(float a, float b) {
    __nv_bfloat162 h = __floats2bfloat162_rn(a, b);
    return *reinterpret_cast<uint32_t*>(&h);
}
static __device__ __forceinline__ uint32_t smem_addr(const void* p) {
    uint32_t a;
    asm("{ .reg .u64 t; cvta.to.shared.u64 t, %1; cvt.u32.u64 %0, t; }" : "=r"(a) : "l"(p));
    return a;
}
static __device__ __forceinline__ void mma16816(float* c, const uint32_t* a,
                                                const uint32_t* b) {
    asm volatile(
        "mma.sync.aligned.m16n8k16.row.col.f32.bf16.bf16.f32 "
        "{%0,%1,%2,%3}, {%4,%5,%6,%7}, {%8,%9}, {%0,%1,%2,%3};"
        : "+f"(c[0]), "+f"(c[1]), "+f"(c[2]), "+f"(c[3])
        : "r"(a[0]), "r"(a[1]), "r"(a[2]), "r"(a[3]), "r"(b[0]), "r"(b[1]));
}
static __device__ __forceinline__ void ldsm4(uint32_t* r, uint32_t addr) {
    asm volatile("ldmatrix.sync.aligned.m8n8.x4.shared.b16 {%0,%1,%2,%3}, [%4];"
        : "=r"(r[0]), "=r"(r[1]), "=r"(r[2]), "=r"(r[3]) : "r"(addr));
}
static __device__ __forceinline__ void ldsm2(uint32_t* r, uint32_t addr) {
    asm volatile("ldmatrix.sync.aligned.m8n8.x2.shared.b16 {%0,%1}, [%2];"
        : "=r"(r[0]), "=r"(r[1]) : "r"(addr));
}
static __device__ __forceinline__ void cpa16(uint32_t d, const void* s) {
    asm volatile("cp.async.ca.shared.global [%0], [%1], 16;" :: "r"(d), "l"(s));
}

#define KPAD    80   // bytes per k-row (40 bf16)
#define BUF_SZ  40960
#define AH_OFF  0
#define AL_OFF  10240
#define BH_OFF  20480
#define BL_OFF  30720

// ldmatrix lane-address components
#define LDSM_A_ROW(lane)  (((lane) & 7) + ((((lane) >> 3) & 1) << 3))
#define LDSM_A_KOFF(lane) ((((lane) >> 4) & 1) * 16)
#define LDSM_B_ROW(lane)  ((lane) & 7)
#define LDSM_B_KOFF(lane) ((((lane) >> 3) & 1) * 16)

// stage one chunk (A: 128x32, B: 128x32, hi+lo) into buffer bufb (256 thr)
#define STAGE_CHUNK(bufb, AHsrc, ALsrc, arow0, ASRCK, k0, BHsrc, BLsrc, nbase, SRCK) \
    do {                                                                        \
        _Pragma("unroll")                                                       \
        for (int it_ = 0; it_ < 2; it_++) {                                     \
            int idx_ = t + it_ * 256;                                           \
            int r_ = idx_ >> 2, seg_ = idx_ & 3;                                \
            size_t ao_ = (size_t)((arow0) + r_) * (ASRCK) + (k0) + seg_ * 8;    \
            cpa16((bufb) + AH_OFF + r_ * KPAD + seg_ * 16, (AHsrc) + ao_);      \
            cpa16((bufb) + AL_OFF + r_ * KPAD + seg_ * 16, (ALsrc) + ao_);      \
            size_t so_ = (size_t)((nbase) + r_) * (SRCK) + (k0) + seg_ * 8;     \
            cpa16((bufb) + BH_OFF + r_ * KPAD + seg_ * 16, (BHsrc) + so_);      \
            cpa16((bufb) + BL_OFF + r_ * KPAD + seg_ * 16, (BLsrc) + so_);      \
        }                                                                       \
        asm volatile("cp.async.commit_group;");                                 \
    } while (0)

// One k-step of the 3-product split GEMM (warp tile 64x32, unchanged)
#define SPLIT_MMA_KSTEP(aBH, aBL, bBH, bBL, ksb, acc)                          \
    do {                                                                       \
        uint32_t af[4][4], bh[4][2], bl[4][2];                                 \
        _Pragma("unroll")                                                      \
        for (int tm = 0; tm < 4; tm++) ldsm4(af[tm], (aBH) + tm * 16 * KPAD + (ksb)); \
        _Pragma("unroll")                                                      \
        for (int tn = 0; tn < 4; tn++) ldsm2(bh[tn], (bBH) + tn * 8 * KPAD + (ksb)); \
        _Pragma("unroll")                                                      \
        for (int tn = 0; tn < 4; tn++) ldsm2(bl[tn], (bBL) + tn * 8 * KPAD + (ksb)); \
        _Pragma("unroll")                                                      \
        for (int tm = 0; tm < 4; tm++)                                         \
            _Pragma("unroll")                                                  \
            for (int tn = 0; tn < 4; tn++)                                     \
                mma16816(acc[tm][tn], af[tm], bh[tn]);                         \
        _Pragma("unroll")                                                      \
        for (int tm = 0; tm < 4; tm++)                                         \
            _Pragma("unroll")                                                  \
            for (int tn = 0; tn < 4; tn++)                                     \
                mma16816(acc[tm][tn], af[tm], bl[tn]);                         \
        _Pragma("unroll")                                                      \
        for (int tm = 0; tm < 4; tm++) ldsm4(af[tm], (aBL) + tm * 16 * KPAD + (ksb)); \
        _Pragma("unroll")                                                      \
        for (int tm = 0; tm < 4; tm++)                                         \
            _Pragma("unroll")                                                  \
            for (int tn = 0; tn < 4; tn++)                                     \
                mma16816(acc[tm][tn], af[tm], bh[tn]);                         \
    } while (0)

// ---------------- weight pack kernels ---------------------------------------
__global__ void k_pack_uv(const float* __restrict__ W1t) {
    int idx = blockIdx.x * 256 + threadIdx.x;
    int n = idx / 768, k = idx - n * 768;
    int isV = (n >= 1536);
    int col = isV ? n - 1536 : n;
    float v = W1t[(size_t)((isV ? 770 : 2) + k) * HT + col];
    __nv_bfloat16 h = __float2bfloat16(v);
    g_wuvh[idx] = h;
    g_wuvl[idx] = __float2bfloat16(v - __bfloat162float(h));
}
__global__ void k_pack_w2(const float* __restrict__ W2t) {
    int idx = blockIdx.x * 256 + threadIdx.x;
    int n = idx / 1536, k = idx - n * 1536;
    float v = W2t[(size_t)k * 768 + n];
    __nv_bfloat16 h = __float2bfloat16(v);
    g_w2h[idx] = h;
    g_w2l[idx] = __float2bfloat16(v - __bfloat162float(h));
}
__global__ void k_pack_w1r(const float* __restrict__ W1r) {
    int idx = blockIdx.x * 256 + threadIdx.x;
    int n = idx / 768, k = idx - n * 768;
    float v = (n < HR) ? W1r[(size_t)(2 + k) * HR + n] : 0.f;
    __nv_bfloat16 h = __float2bfloat16(v);
    g_w1rh[idx] = h;
    g_w1rl[idx] = __float2bfloat16(v - __bfloat162float(h));
}

// ---------------- kernel 0: triangle rank -> edge table ---------------------
__global__ void k_trimap() {
    int e = blockIdx.x * 1024 + threadIdx.x;
    int b = e >> 12, i = (e >> 6) & 63, j = e & 63;
    if (i <= j) {
        int rank = b * TRI_B + i * (129 - i) / 2 + (j - i);
        g_tri[rank] = e;
    }
}

// ---------------- kernel 1: agg --------------------------------------------
__global__ void k_agg(const float* __restrict__ x, const float* __restrict__ adjs,
                      const float* __restrict__ flags) {
    int bi = blockIdx.x;
    int b = bi >> 6, i = bi & 63;
    int f = threadIdx.x;
    __shared__ float a0s[64], a1s[64];
    float fi = flags[b * 64 + i];
    if (threadIdx.x < 64) {
        int j = threadIdx.x;
        float fj = flags[b * 64 + j];
        float a = adjs[(size_t)bi * 64 + j];
        float m = fi * fj;
        a0s[j] = a * m;
        a1s[j] = (1.f - a) * m;
    }
    __syncthreads();
    float s0 = 0.f, s1 = 0.f;
    const float* xb = x + (size_t)b * NNODE * FIN;
    #pragma unroll 4
    for (int j = 0; j < 64; j++) {
        float xv = xb[j * FIN + f];
        s0 += a0s[j] * xv;
        s1 += a1s[j] * xv;
    }
    g_agg[bi * 256 + f] = s0;
    g_agg[bi * 256 + 128 + f] = s1;
}

// ---------------- kernel 2: GIN MLPs -> x_o (+ bf16 hi/lo split) ------------
__global__ void k_gin(const float* __restrict__ x, const float* __restrict__ flags,
                      const float* __restrict__ Wg, const float* __restrict__ bg,
                      const float* __restrict__ Wout, const float* __restrict__ bout,
                      float* __restrict__ out_xo) {
    __shared__ float aggs[8][256];
    __shared__ float xs[8][128];
    __shared__ float hs[8][256];
    __shared__ float fl[8];
    int r0 = blockIdx.x * 8;
    int t = threadIdx.x;
    for (int idx = t; idx < 8 * 256; idx += 256)
        aggs[idx >> 8][idx & 255] = g_agg[r0 * 256 + idx];
    for (int idx = t; idx < 8 * 128; idx += 256)
        xs[idx >> 7][idx & 127] = x[(size_t)r0 * 128 + idx];
    if (t < 8) fl[t] = flags[r0 + t];
    __syncthreads();
    {
        float acc[8];
        float bgv = bg[t];
        #pragma unroll
        for (int r = 0; r < 8; r++) acc[r] = bgv;
        for (int k = 0; k < 256; k++) {
            float w = Wg[k * 256 + t];
            #pragma unroll
            for (int r = 0; r < 8; r++) acc[r] += aggs[r][k] * w;
        }
        #pragma unroll
        for (int r = 0; r < 8; r++) hs[r][t] = elu_f(acc[r]) * fl[r];
    }
    __syncthreads();
    float acc[3][8];
    #pragma unroll
    for (int c = 0; c < 3; c++) {
        float bo = bout[t + c * 256];
        #pragma unroll
        for (int r = 0; r < 8; r++) acc[c][r] = bo;
    }
    for (int k = 0; k < 128; k++) {
        float o[8];
        #pragma unroll
        for (int r = 0; r < 8; r++) o[r] = xs[r][k];
        #pragma unroll
        for (int c = 0; c < 3; c++) {
            float w = Wout[k * 768 + t + c * 256];
            #pragma unroll
            for (int r = 0; r < 8; r++) acc[c][r] += o[r] * w;
        }
    }
    for (int k = 0; k < 256; k++) {
        float o[8];
        #pragma unroll
        for (int r = 0; r < 8; r++) o[r] = hs[r][k];
        #pragma unroll
        for (int c = 0; c < 3; c++) {
            float w = Wout[(128 + k) * 768 + t + c * 256];
            #pragma unroll
            for (int r = 0; r < 8; r++) acc[c][r] += o[r] * w;
        }
    }
    #pragma unroll
    for (int c = 0; c < 3; c++)
        #pragma unroll
        for (int r = 0; r < 8; r++) {
            size_t idx = (size_t)(r0 + r) * 768 + t + c * 256;
            float val = tanhf(acc[c][r]) * fl[r];
            out_xo[idx] = val;
            __nv_bfloat16 h = __float2bfloat16(val);
            g_xh[idx] = h;
            g_xl[idx] = __float2bfloat16(val - __bfloat162float(h));
        }
}

// ---------------- kernel 3: U,V via pipelined mma (128x128 tile, occ 2) -----
#define UV_SMEM (2 * BUF_SZ)

__global__ void __launch_bounds__(256, 2)
k_uv_mma() {
    extern __shared__ char sm[];
    uint32_t sb = smem_addr(sm);
    int t = threadIdx.x;
    int m0 = blockIdx.y * 128;
    int ng0 = blockIdx.x * 128;
    const int isU = (ng0 < HT);

    int wid = t >> 5, lane = t & 31;
    int mw = (wid & 1) * 64, nw = (wid >> 1) * 32;
    int row4 = lane >> 2, quad = lane & 3;
    int laneA = (mw + LDSM_A_ROW(lane)) * KPAD + LDSM_A_KOFF(lane);
    int laneB = (nw + LDSM_B_ROW(lane)) * KPAD + LDSM_B_KOFF(lane);

    float acc[4][4][4];
    #pragma unroll
    for (int tm = 0; tm < 4; tm++)
        #pragma unroll
        for (int tn = 0; tn < 4; tn++)
            #pragma unroll
            for (int q = 0; q < 4; q++) acc[tm][tn][q] = 0.f;

    STAGE_CHUNK(sb, g_xh, g_xl, m0, 768, 0, g_wuvh, g_wuvl, ng0, 768);
    for (int c = 0; c < 24; c++) {
        uint32_t cur = sb + (c & 1) * BUF_SZ;
        uint32_t nxt = sb + ((c + 1) & 1) * BUF_SZ;
        __syncthreads();
        if (c + 1 < 24) {
            STAGE_CHUNK(nxt, g_xh, g_xl, m0, 768, (c + 1) * 32, g_wuvh, g_wuvl, ng0, 768);
            asm volatile("cp.async.wait_group 1;" ::: "memory");
        } else {
            asm volatile("cp.async.wait_group 0;" ::: "memory");
        }
        __syncthreads();
        #pragma unroll
        for (int ks = 0; ks < 2; ks++)
            SPLIT_MMA_KSTEP(cur + AH_OFF + laneA, cur + AL_OFF + laneA,
                            cur + BH_OFF + laneB, cur + BL_OFF + laneB, ks * 32, acc);
    }

    float* Obase = (isU ? g_U : g_V);
    int c0 = isU ? ng0 : ng0 - HT;
    #pragma unroll
    for (int tm = 0; tm < 4; tm++) {
        int gr = m0 + mw + tm * 16 + row4;
        #pragma unroll
        for (int tn = 0; tn < 4; tn++) {
            int gc = c0 + nw + tn * 8 + quad * 2;
            float* p0 = Obase + (size_t)gr * HT + gc;
            float* p1 = Obase + (size_t)(gr + 8) * HT + gc;
            *(float2*)p0 = make_float2(acc[tm][tn][0], acc[tm][tn][1]);
            *(float2*)p1 = make_float2(acc[tm][tn][2], acc[tm][tn][3]);
        }
    }
}

// ---------------- kernel 4a: adjacency sums (parallel, SMEM-tiled) ----------
__global__ void k_statA(const float* __restrict__ adjs, const float* __restrict__ flags) {
    __shared__ float a[64][65];
    __shared__ float fl[64];
    __shared__ float red[64];
    int b = blockIdx.x;
    int i = threadIdx.x;
    for (int idx = i; idx < 4096; idx += 64)
        a[idx >> 6][idx & 63] = adjs[(size_t)b * 4096 + idx];
    fl[i] = flags[b * 64 + i];
    __syncthreads();
    float fi = fl[i];
    float r0 = 0.f, r1 = 0.f, c0 = 0.f, c1 = 0.f;
    float s0 = 0.f, s1 = 0.f, s00 = 0.f, s01 = 0.f, s11 = 0.f;
    #pragma unroll 4
    for (int j = 0; j < 64; j++) {
        float m = fi * fl[j];
        float av = a[i][j];
        float a0 = av * m, a1 = (1.f - av) * m;
        r0 += a0; r1 += a1;
        s0 += a0; s1 += a1;
        s00 += a0 * a0; s01 += a0 * a1; s11 += a1 * a1;
        float at = a[j][i];
        c0 += at * m; c1 += (1.f - at) * m;
    }
    int bi = b * 64 + i;
    g_r0[bi] = r0; g_r1[bi] = r1; g_c0s[bi] = c0; g_c1s[bi] = c1;
    float vals[5] = {s0, s1, s00, s01, s11};
    for (int v = 0; v < 5; v++) {
        red[i] = vals[v];
        __syncthreads();
        for (int off = 32; off > 0; off >>= 1) {
            if (i < off) red[i] += red[i + off];
            __syncthreads();
        }
        if (i == 0) g_scp[b * 5 + v] = red[0];
        __syncthreads();
    }
}

// ---------------- kernel 4b: per-(batch,k) partials --------------------------
__global__ void k_statB() {
    int k = blockIdx.x * 128 + threadIdx.x;
    int b = blockIdx.y;
    float ub = 0.f, vb = 0.f, u2 = 0.f, v2 = 0.f, T0 = 0.f, T1 = 0.f;
    #pragma unroll 4
    for (int r = 0; r < 64; r++) {
        int bi = b * 64 + r;
        float u = g_U[(size_t)bi * HT + k];
        float v = g_V[(size_t)bi * HT + k];
        ub += u; vb += v; u2 += u * u; v2 += v * v;
        T0 += u * g_r0[bi] + v * g_c0s[bi];
        T1 += u * g_r1[bi] + v * g_c1s[bi];
    }
    g_part[0 * 16 * HT + b * HT + k] = 64.f * (ub + vb);
    g_part[1 * 16 * HT + b * HT + k] = 64.f * (u2 + v2) + 2.f * ub * vb;
    g_part[2 * 16 * HT + b * HT + k] = T0;
    g_part[3 * 16 * HT + b * HT + k] = T1;
}

// ---------------- kernel 4c: finalize BN constants ---------------------------
__global__ void k_statC(const float* __restrict__ W1t, const float* __restrict__ b1t,
                        const float* __restrict__ gamma, const float* __restrict__ beta) {
    int k = blockIdx.x * 256 + threadIdx.x;
    float w0 = W1t[k], w1 = W1t[HT + k];
    float sumz = 0.f, sqb = 0.f, T0 = 0.f, T1 = 0.f;
    float S0 = 0.f, S1 = 0.f, S00 = 0.f, S01 = 0.f, S11 = 0.f;
    for (int b = 0; b < 16; b++) {
        sumz += g_part[0 * 16 * HT + b * HT + k];
        sqb  += g_part[1 * 16 * HT + b * HT + k];
        T0   += g_part[2 * 16 * HT + b * HT + k];
        T1   += g_part[3 * 16 * HT + b * HT + k];
        S0 += g_scp[b * 5 + 0]; S1 += g_scp[b * 5 + 1];
        S00 += g_scp[b * 5 + 2]; S01 += g_scp[b * 5 + 3]; S11 += g_scp[b * 5 + 4];
    }
    float sz = sumz + S0 * w0 + S1 * w1;
    float sq = sqb + 2.f * (w0 * T0 + w1 * T1)
             + S00 * w0 * w0 + 2.f * S01 * w0 * w1 + S11 * w1 * w1;
    const float inv = 1.f / 65536.f;
    float mu_z = sz * inv;
    float var = fmaxf(sq * inv - mu_z * mu_z, 0.f);
    float mu = mu_z + b1t[k];
    float c1 = gamma[k] * rsqrtf(var + 1e-5f);
    g_c1[k] = c1;
    g_c2[k] = beta[k] - mu * c1;
}

// ---------------- kernel 5b: h2sum on triangle (balanced pairs) -------------
__global__ void __launch_bounds__(384)
k_agen_tri(const float* __restrict__ adjs, const float* __restrict__ flags,
           const float* __restrict__ W1t) {
    int blk = blockIdx.x;
    int b = blk >> 5, p = blk & 31;
    int c4 = threadIdx.x * 4;
    float4 w0 = __ldg((const float4*)(W1t + c4));
    float4 w1 = __ldg((const float4*)(W1t + HT + c4));
    float4 c1 = *(const float4*)(g_c1 + c4);
    float4 c2 = *(const float4*)(g_c2 + c4);
    #pragma unroll
    for (int half = 0; half < 2; half++) {
        int i = half ? (63 - p) : p;
        int bi = b * 64 + i;
        float4 ui = *(const float4*)(g_U + (size_t)bi * HT + c4);
        float4 vi = *(const float4*)(g_V + (size_t)bi * HT + c4);
        float fi = __ldg(flags + b * 64 + i);
        size_t rank0 = (size_t)b * TRI_B + i * (129 - i) / 2;
        for (int j = i; j < 64; j++) {
            float fj = __ldg(flags + b * 64 + j);
            float mk = fi * fj;
            float aij = __ldg(adjs + (size_t)b * 4096 + i * 64 + j);
            float aji = __ldg(adjs + (size_t)b * 4096 + j * 64 + i);
            float a0ij = aij * mk, a1ij = (1.f - aij) * mk;
            float a0ji = aji * mk, a1ji = (1.f - aji) * mk;
            float4 uj = *(const float4*)(g_U + (size_t)(b * 64 + j) * HT + c4);
            float4 vj = *(const float4*)(g_V + (size_t)(b * 64 + j) * HT + c4);
            float s0 = elu_f((ui.x + vj.x + a0ij * w0.x + a1ij * w1.x) * c1.x + c2.x)
                     + elu_f((uj.x + vi.x + a0ji * w0.x + a1ji * w1.x) * c1.x + c2.x);
            float s1 = elu_f((ui.y + vj.y + a0ij * w0.y + a1ij * w1.y) * c1.y + c2.y)
                     + elu_f((uj.y + vi.y + a0ji * w0.y + a1ji * w1.y) * c1.y + c2.y);
            float s2 = elu_f((ui.z + vj.z + a0ij * w0.z + a1ij * w1.z) * c1.z + c2.z)
                     + elu_f((uj.z + vi.z + a0ji * w0.z + a1ji * w1.z) * c1.z + c2.z);
            float s3 = elu_f((ui.w + vj.w + a0ij * w0.w + a1ij * w1.w) * c1.w + c2.w)
                     + elu_f((uj.w + vi.w + a0ji * w0.w + a1ji * w1.w) * c1.w + c2.w);
            float r0 = s0 - __bfloat162float(__float2bfloat16(s0));
            float r1 = s1 - __bfloat162float(__float2bfloat16(s1));
            float r2 = s2 - __bfloat162float(__float2bfloat16(s2));
            float r3 = s3 - __bfloat162float(__float2bfloat16(s3));
            size_t row = (rank0 + (j - i)) * HT + c4;
            *(uint2*)(g_hh + row) = make_uint2(pack2(s0, s1), pack2(s2, s3));
            *(uint2*)(g_hl + row) = make_uint2(pack2(r0, r1), pack2(r2, r3));
        }
    }
}

// ---------------- kernel 6: triangle translate GEMM -> S (128x128, occ 2) ---
#define GP_MKS  (2 * BUF_SZ)
#define GP_SMEM (2 * BUF_SZ + 512)

__global__ void __launch_bounds__(256, 2)
k_gemm2_tri(const float* __restrict__ flags, const float* __restrict__ b2t) {
    extern __shared__ char sm[];
    uint32_t sb = smem_addr(sm);
    float* mks = (float*)(sm + GP_MKS);
    int t = threadIdx.x;
    int m0 = blockIdx.y * 128, n0g = blockIdx.x * 128;

    if (t < 128) {
        int e = __ldg(g_tri + m0 + t);
        int b = e >> 12, i = (e >> 6) & 63, j = e & 63;
        mks[t] = __ldg(flags + b * 64 + i) * __ldg(flags + b * 64 + j);
    }

    int wid = t >> 5, lane = t & 31;
    int mw = (wid & 1) * 64, nw = (wid >> 1) * 32;
    int row4 = lane >> 2, quad = lane & 3;
    int laneA = (mw + LDSM_A_ROW(lane)) * KPAD + LDSM_A_KOFF(lane);
    int laneB = (nw + LDSM_B_ROW(lane)) * KPAD + LDSM_B_KOFF(lane);

    float acc[4][4][4];
    #pragma unroll
    for (int tm = 0; tm < 4; tm++)
        #pragma unroll
        for (int tn = 0; tn < 4; tn++)
            #pragma unroll
            for (int q = 0; q < 4; q++) acc[tm][tn][q] = 0.f;

    STAGE_CHUNK(sb, g_hh, g_hl, m0, HT, 0, g_w2h, g_w2l, n0g, 1536);
    for (int c = 0; c < 48; c++) {
        uint32_t cur = sb + (c & 1) * BUF_SZ;
        uint32_t nxt = sb + ((c + 1) & 1) * BUF_SZ;
        __syncthreads();
        if (c + 1 < 48) {
            STAGE_CHUNK(nxt, g_hh, g_hl, m0, HT, (c + 1) * 32, g_w2h, g_w2l, n0g, 1536);
            asm volatile("cp.async.wait_group 1;" ::: "memory");
        } else {
            asm volatile("cp.async.wait_group 0;" ::: "memory");
        }
        __syncthreads();
        #pragma unroll
        for (int ks = 0; ks < 2; ks++)
            SPLIT_MMA_KSTEP(cur + AH_OFF + laneA, cur + AL_OFF + laneA,
                            cur + BH_OFF + laneB, cur + BL_OFF + laneB, ks * 32, acc);
    }

    #pragma unroll
    for (int tm = 0; tm < 4; tm++) {
        int r0 = mw + tm * 16 + row4;
        float mk0 = mks[r0], mk1 = mks[r0 + 8];
        size_t gr0 = (size_t)(m0 + r0) * 768;
        size_t gr1 = (size_t)(m0 + r0 + 8) * 768;
        #pragma unroll
        for (int tn = 0; tn < 4; tn++) {
            int gc = n0g + nw + tn * 8 + quad * 2;
            float bx = 2.f * __ldg(b2t + gc), by = 2.f * __ldg(b2t + gc + 1);
            float s00 = (acc[tm][tn][0] + bx) * mk0, s01 = (acc[tm][tn][1] + by) * mk0;
            float s10 = (acc[tm][tn][2] + bx) * mk1, s11 = (acc[tm][tn][3] + by) * mk1;
            float r00 = s00 - __bfloat162float(__float2bfloat16(s00));
            float r01 = s01 - __bfloat162float(__float2bfloat16(s01));
            float r10 = s10 - __bfloat162float(__float2bfloat16(s10));
            float r11 = s11 - __bfloat162float(__float2bfloat16(s11));
            *(uint32_t*)(g_ssh + gr0 + gc) = pack2(s00, s01);
            *(uint32_t*)(g_ssl + gr0 + gc) = pack2(r00, r01);
            *(uint32_t*)(g_ssh + gr1 + gc) = pack2(s10, s11);
            *(uint32_t*)(g_ssl + gr1 + gc) = pack2(r10, r11);
        }
    }
}

// ---------------- kernel 7: triangle final_read_score (128-n passes, occ 2) -
#define ST_A0IJ (2 * BUF_SZ)
#define ST_A1IJ (2 * BUF_SZ + 512)
#define ST_A0JI (2 * BUF_SZ + 1024)
#define ST_A1JI (2 * BUF_SZ + 1536)
#define ST_ESM  (2 * BUF_SZ + 2048)
#define ST_RED  (2 * BUF_SZ + 2560)
#define ST_SMEM (2 * BUF_SZ + 2560 + 4096)

__global__ void __launch_bounds__(256, 2)
k_score_tri(const float* __restrict__ adjs, const float* __restrict__ flags,
            const float* __restrict__ W1r, const float* __restrict__ b1r,
            const float* __restrict__ W2r, const float* __restrict__ b2r,
            float* __restrict__ out_score) {
    extern __shared__ char sm[];
    uint32_t sb = smem_addr(sm);
    float* a0ijs = (float*)(sm + ST_A0IJ);
    float* a1ijs = (float*)(sm + ST_A1IJ);
    float* a0jis = (float*)(sm + ST_A0JI);
    float* a1jis = (float*)(sm + ST_A1JI);
    int*   esm   = (int*)(sm + ST_ESM);
    float* red   = (float*)(sm + ST_RED);   // [128][4] ij then [128][4] ji
    int t = threadIdx.x;
    int m0 = blockIdx.x * 128;

    if (t < 128) {
        int e = __ldg(g_tri + m0 + t);
        esm[t] = e;
        int b = e >> 12, i = (e >> 6) & 63, j = e & 63;
        float mk = __ldg(flags + b * 64 + i) * __ldg(flags + b * 64 + j);
        float aij = __ldg(adjs + e);
        float aji = __ldg(adjs + (b << 12) + (j << 6) + i);
        a0ijs[t] = aij * mk; a1ijs[t] = (1.f - aij) * mk;
        a0jis[t] = aji * mk; a1jis[t] = (1.f - aji) * mk;
    }

    int wid = t >> 5, lane = t & 31;
    int mw = (wid & 1) * 64, nw = (wid >> 1) * 32;
    int row4 = lane >> 2, quad = lane & 3;
    int laneA = (mw + LDSM_A_ROW(lane)) * KPAD + LDSM_A_KOFF(lane);
    int laneB = (nw + LDSM_B_ROW(lane)) * KPAD + LDSM_B_KOFF(lane);

    float sij[4][2], sji[4][2];
    #pragma unroll
    for (int tm = 0; tm < 4; tm++) {
        sij[tm][0] = 0.f; sij[tm][1] = 0.f;
        sji[tm][0] = 0.f; sji[tm][1] = 0.f;
    }
    __syncthreads();

    STAGE_CHUNK(sb, g_ssh, g_ssl, m0, 768, 0, g_w1rh, g_w1rl, 0, 768);
    for (int nc = 0; nc < 14; nc++) {
        int n0 = nc * 128;
        float acc[4][4][4];
        #pragma unroll
        for (int tn = 0; tn < 4; tn++)
            #pragma unroll
            for (int cq = 0; cq < 2; cq++) {
                int n = n0 + nw + tn * 8 + quad * 2 + cq;
                float br = (n < HR) ? __ldg(b1r + n) : 0.f;
                #pragma unroll
                for (int tm = 0; tm < 4; tm++) {
                    acc[tm][tn][cq] = br;
                    acc[tm][tn][2 + cq] = br;
                }
            }
        for (int c = 0; c < 24; c++) {
            uint32_t cur = sb + (c & 1) * BUF_SZ;
            uint32_t nxt = sb + ((c + 1) & 1) * BUF_SZ;
            __syncthreads();
            if (c + 1 < 24) {
                STAGE_CHUNK(nxt, g_ssh, g_ssl, m0, 768, (c + 1) * 32, g_w1rh, g_w1rl, n0, 768);
                asm volatile("cp.async.wait_group 1;" ::: "memory");
            } else {
                asm volatile("cp.async.wait_group 0;" ::: "memory");
            }
            __syncthreads();
            #pragma unroll
            for (int ks = 0; ks < 2; ks++)
                SPLIT_MMA_KSTEP(cur + AH_OFF + laneA, cur + AL_OFF + laneA,
                                cur + BH_OFF + laneB, cur + BL_OFF + laneB, ks * 32, acc);
        }
        // prefetch next nc's chunk 0 (buffer 0 free) before epilogue
        if (nc + 1 < 14)
            STAGE_CHUNK(sb, g_ssh, g_ssl, m0, 768, 0, g_w1rh, g_w1rl, (nc + 1) * 128, 768);
        // epilogue: elu both orientations, dot with W2r
        #pragma unroll
        for (int tn = 0; tn < 4; tn++)
            #pragma unroll
            for (int cq = 0; cq < 2; cq++) {
                int n = n0 + nw + tn * 8 + quad * 2 + cq;
                bool ok = n < HR;
                float w0 = ok ? __ldg(W1r + n) : 0.f;
                float w1 = ok ? __ldg(W1r + HR + n) : 0.f;
                float w2 = ok ? __ldg(W2r + n) : 0.f;
                #pragma unroll
                for (int tm = 0; tm < 4; tm++) {
                    int r0 = mw + tm * 16 + row4;
                    float g0 = acc[tm][tn][cq], g1 = acc[tm][tn][2 + cq];
                    sij[tm][0] += elu_f(g0 + a0ijs[r0] * w0 + a1ijs[r0] * w1) * w2;
                    sji[tm][0] += elu_f(g0 + a0jis[r0] * w0 + a1jis[r0] * w1) * w2;
                    sij[tm][1] += elu_f(g1 + a0ijs[r0 + 8] * w0 + a1ijs[r0 + 8] * w1) * w2;
                    sji[tm][1] += elu_f(g1 + a0jis[r0 + 8] * w0 + a1jis[r0 + 8] * w1) * w2;
                }
            }
    }
    #pragma unroll
    for (int off = 1; off <= 2; off <<= 1)
        #pragma unroll
        for (int tm = 0; tm < 4; tm++) {
            sij[tm][0] += __shfl_xor_sync(0xffffffffu, sij[tm][0], off);
            sij[tm][1] += __shfl_xor_sync(0xffffffffu, sij[tm][1], off);
            sji[tm][0] += __shfl_xor_sync(0xffffffffu, sji[tm][0], off);
            sji[tm][1] += __shfl_xor_sync(0xffffffffu, sji[tm][1], off);
        }
    __syncthreads();
    if (quad == 0) {
        int wn = wid >> 1;   // 0..3
        #pragma unroll
        for (int tm = 0; tm < 4; tm++) {
            int r0 = mw + tm * 16 + row4;
            red[r0 * 4 + wn] = sij[tm][0];
            red[(r0 + 8) * 4 + wn] = sij[tm][1];
            red[512 + r0 * 4 + wn] = sji[tm][0];
            red[512 + (r0 + 8) * 4 + wn] = sji[tm][1];
        }
    }
    __syncthreads();
    if (t < 128) {
        float s1 = 0.f, s2 = 0.f;
        #pragma unroll
        for (int w4 = 0; w4 < 4; w4++) {
            s1 += red[t * 4 + w4];
            s2 += red[512 + t * 4 + w4];
        }
        int e = esm[t];
        int b = e >> 12, i = (e >> 6) & 63, j = e & 63;
        float b2 = b2r[0];
        out_score[e] = (i == j) ? 0.f : (s1 + b2);
        if (i != j)
            out_score[(b << 12) + (j << 6) + i] = s2 + b2;
    }
}

// ---------------- launch -----------------------------------------------------
extern "C" void kernel_launch(void* const* d_in, const int* in_sizes, int n_in,
                              void* d_out, int out_size) {
    const float* x     = (const float*)d_in[0];
    const float* adjs  = (const float*)d_in[1];
    const float* flags = (const float*)d_in[2];
    const float* Wg    = (const float*)d_in[3];
    const float* bg    = (const float*)d_in[4];
    const float* Wout  = (const float*)d_in[5];
    const float* bout  = (const float*)d_in[6];
    const float* W1t   = (const float*)d_in[7];
    const float* b1t   = (const float*)d_in[8];
    const float* gamma = (const float*)d_in[9];
    const float* beta  = (const float*)d_in[10];
    const float* W2t   = (const float*)d_in[11];
    const float* b2t   = (const float*)d_in[12];
    const float* W1r   = (const float*)d_in[13];
    const float* b1r   = (const float*)d_in[14];
    const float* W2r   = (const float*)d_in[15];
    const float* b2r   = (const float*)d_in[16];

    float* out_score = (float*)d_out;             // [B,N,N] = 65536
    float* out_xo    = (float*)d_out + NEDGE;     // [B,N,768]

    cudaFuncSetAttribute(k_uv_mma, cudaFuncAttributeMaxDynamicSharedMemorySize, UV_SMEM);
    cudaFuncSetAttribute(k_gemm2_tri, cudaFuncAttributeMaxDynamicSharedMemorySize, GP_SMEM);
    cudaFuncSetAttribute(k_score_tri, cudaFuncAttributeMaxDynamicSharedMemorySize, ST_SMEM);

    k_pack_uv<<<3072 * 768 / 256, 256>>>(W1t);
    k_pack_w2<<<768 * 1536 / 256, 256>>>(W2t);
    k_pack_w1r<<<HRP * 768 / 256, 256>>>(W1r);
    k_trimap<<<64, 1024>>>();
    k_statA<<<16, 64>>>(adjs, flags);
    k_agg<<<NROW, 128>>>(x, adjs, flags);
    k_gin<<<NROW / 8, 256>>>(x, flags, Wg, bg, Wout, bout, out_xo);
    k_uv_mma<<<dim3(24, 8), 256, UV_SMEM>>>();
    k_statB<<<dim3(12, 16), 128>>>();
    k_statC<<<6, 256>>>(W1t, b1t, gamma, beta);
    k_agen_tri<<<512, 384>>>(adjs, flags, W1t);
    k_gemm2_tri<<<dim3(6, 260), 256, GP_SMEM>>>(flags, b2t);
    k_score_tri<<<260, 256, ST_SMEM>>>(adjs, flags, W1r, b1r, W2r, b2r, out_score);
}